// round 1
// baseline (speedup 1.0000x reference)
#include <cuda_runtime.h>
#include <math.h>

// Problem constants
#define NB  2
#define CC  768
#define SS  4096
#define LL  1024
#define HH  8
#define DD  96
#define TCH 384
#define FF  1536
#define NH  (NB*HH)

// Scratch (__device__ globals; no allocation allowed)
static __device__ float g_v3[NB*CC*LL];    // v * tm^3  (N, C=h*d, L)
static __device__ float g_k [NB*CC*LL];    // k         (N, C, L)
static __device__ float g_q [NB*CC*SS];    // q         (N, C, S)
static __device__ float g_y [NB*CC*SS];    // y = x + x_p
static __device__ float g_h [NB*FF*SS];    // relu(W1 y)
static __device__ float g_denom[NH*SS];    // sum_l exp(coef)*tm

__global__ void zero_denom_kernel() {
    int i = blockIdx.x * blockDim.x + threadIdx.x;
    if (i < NH*SS) g_denom[i] = 0.f;
}

enum { EPI_NONE = 0, EPI_V3 = 1, EPI_RELU = 2, EPI_ADDX = 3 };

// Generic NN SGEMM: C[n] = A (MxK, row-major, shared over batch) * B[n] (KxN row-major)
// BM=BN=128, BK=16, 256 threads, 8x8 microtile. All dims multiples of tile sizes.
template<int EPI>
__global__ void __launch_bounds__(256) gemm_nn_kernel(
    const float* __restrict__ A, const float* __restrict__ Bb,
    float* __restrict__ Cb, int M, int Nn, int K,
    const float* __restrict__ ep)
{
    __shared__ float As[16][128];
    __shared__ float Bs[16][128];
    const int n  = blockIdx.z;
    const float* B = Bb + (size_t)n * K * Nn;
    float*      Cp = Cb + (size_t)n * M * Nn;
    const int m0 = blockIdx.y * 128, n0 = blockIdx.x * 128;
    const int tid = threadIdx.x, ty = tid >> 4, tx = tid & 15;

    float acc[8][8];
#pragma unroll
    for (int i = 0; i < 8; i++)
#pragma unroll
        for (int j = 0; j < 8; j++) acc[i][j] = 0.f;

    for (int k0 = 0; k0 < K; k0 += 16) {
#pragma unroll
        for (int t = 0; t < 2; t++) {           // A tile: 128 rows x 16 k, transpose to As[k][m]
            int idx = tid + t * 256;
            int row = idx >> 2, c4 = idx & 3;
            float4 a = *(const float4*)(A + (size_t)(m0 + row) * K + k0 + c4 * 4);
            As[c4*4+0][row] = a.x; As[c4*4+1][row] = a.y;
            As[c4*4+2][row] = a.z; As[c4*4+3][row] = a.w;
        }
#pragma unroll
        for (int t = 0; t < 2; t++) {           // B tile: 16 k x 128 n, direct
            int idx = tid + t * 256;
            int row = idx >> 5, c4 = idx & 31;
            *(float4*)&Bs[row][c4*4] =
                *(const float4*)(B + (size_t)(k0 + row) * Nn + n0 + c4 * 4);
        }
        __syncthreads();
#pragma unroll
        for (int kk = 0; kk < 16; kk++) {
            float a[8], b[8];
            *(float4*)&a[0] = *(float4*)&As[kk][ty*8];
            *(float4*)&a[4] = *(float4*)&As[kk][ty*8+4];
            *(float4*)&b[0] = *(float4*)&Bs[kk][tx*8];
            *(float4*)&b[4] = *(float4*)&Bs[kk][tx*8+4];
#pragma unroll
            for (int i = 0; i < 8; i++)
#pragma unroll
                for (int j = 0; j < 8; j++)
                    acc[i][j] += a[i] * b[j];
        }
        __syncthreads();
    }

    float cm[8];
    if (EPI == EPI_V3) {
#pragma unroll
        for (int j = 0; j < 8; j++) {
            float t = ep[(size_t)n * Nn + n0 + tx*8 + j];
            cm[j] = t * t * t;
        }
    }
#pragma unroll
    for (int i = 0; i < 8; i++) {
        int row = m0 + ty*8 + i;
        float v[8];
#pragma unroll
        for (int j = 0; j < 8; j++) {
            float val = acc[i][j];
            if (EPI == EPI_V3)   val *= cm[j];
            if (EPI == EPI_RELU) val = fmaxf(val, 0.f);
            v[j] = val;
        }
        size_t co = (size_t)row * Nn + n0 + tx*8;
        if (EPI == EPI_ADDX) {
            const float* xr = ep + (size_t)n * M * Nn;
            float4 x0 = *(const float4*)(xr + co);
            float4 x1 = *(const float4*)(xr + co + 4);
            v[0]+=x0.x; v[1]+=x0.y; v[2]+=x0.z; v[3]+=x0.w;
            v[4]+=x1.x; v[5]+=x1.y; v[6]+=x1.z; v[7]+=x1.w;
        }
        *(float4*)(Cp + co)     = make_float4(v[0],v[1],v[2],v[3]);
        *(float4*)(Cp + co + 4) = make_float4(v[4],v[5],v[6],v[7]);
    }
}

// coef[s,l] = (1/sqrt(96)) * im[n,s] * sum_d q[n,h,d,s] * k[n,h,d,l]
// Stores PRE-mask coef into proj slot; accumulates denom[s] = sum_l exp(coef)*tm[l].
__global__ void __launch_bounds__(256) coef_kernel(
    const float* __restrict__ im, const float* __restrict__ tmask,
    float* __restrict__ proj)
{
    __shared__ float As[16][128];
    __shared__ float Bs[16][128];
    __shared__ float red[128][16];
    const int nh = blockIdx.z, n = nh >> 3, h = nh & 7;
    const float* Aq = g_q + (size_t)n * CC * SS + (size_t)h * DD * SS;  // [k][s]
    const float* Bk = g_k + (size_t)n * CC * LL + (size_t)h * DD * LL;  // [k][l]
    const int m0 = blockIdx.y * 128, n0 = blockIdx.x * 128;
    const int tid = threadIdx.x, ty = tid >> 4, tx = tid & 15;

    float acc[8][8];
#pragma unroll
    for (int i = 0; i < 8; i++)
#pragma unroll
        for (int j = 0; j < 8; j++) acc[i][j] = 0.f;

    for (int k0 = 0; k0 < DD; k0 += 16) {
#pragma unroll
        for (int t = 0; t < 2; t++) {
            int idx = tid + t * 256;
            int row = idx >> 5, c4 = idx & 31;
            *(float4*)&As[row][c4*4] =
                *(const float4*)(Aq + (size_t)(k0 + row) * SS + m0 + c4 * 4);
            *(float4*)&Bs[row][c4*4] =
                *(const float4*)(Bk + (size_t)(k0 + row) * LL + n0 + c4 * 4);
        }
        __syncthreads();
#pragma unroll
        for (int kk = 0; kk < 16; kk++) {
            float a[8], b[8];
            *(float4*)&a[0] = *(float4*)&As[kk][ty*8];
            *(float4*)&a[4] = *(float4*)&As[kk][ty*8+4];
            *(float4*)&b[0] = *(float4*)&Bs[kk][tx*8];
            *(float4*)&b[4] = *(float4*)&Bs[kk][tx*8+4];
#pragma unroll
            for (int i = 0; i < 8; i++)
#pragma unroll
                for (int j = 0; j < 8; j++)
                    acc[i][j] += a[i] * b[j];
        }
        __syncthreads();
    }

    const float inv = 0.1020620726159657f;  // 1/sqrt(96)
    float tmv[8];
#pragma unroll
    for (int j = 0; j < 8; j++) tmv[j] = tmask[(size_t)n * LL + n0 + tx*8 + j];
    float* pr = proj + (size_t)nh * SS * LL;
#pragma unroll
    for (int i = 0; i < 8; i++) {
        int s = m0 + ty*8 + i;
        float sc = im[(size_t)n * SS + s] * inv;
        float v[8]; float rs = 0.f;
#pragma unroll
        for (int j = 0; j < 8; j++) {
            float c = acc[i][j] * sc;
            v[j] = c;
            rs += expf(c) * tmv[j];
        }
        size_t co = (size_t)s * LL + n0 + tx*8;
        *(float4*)(pr + co)     = make_float4(v[0],v[1],v[2],v[3]);
        *(float4*)(pr + co + 4) = make_float4(v[4],v[5],v[6],v[7]);
        red[ty*8 + i][tx] = rs;
    }
    __syncthreads();
    if (tid < 128) {
        float sum = 0.f;
#pragma unroll
        for (int j = 0; j < 16; j++) sum += red[tid][j];
        atomicAdd(&g_denom[(size_t)nh * SS + m0 + tid], sum);
    }
}

// x_p[d,s] = (1/(denom[s]+1e-6)) * sum_l v3[d,l] * exp(coef[s,l]);  y = x + x_p
// Also overwrites proj with coef*tm (final output). M=96 (all d in one block), BN=128 s, BK=16 l.
__global__ void __launch_bounds__(256) xp_kernel(
    const float* __restrict__ x, const float* __restrict__ tmask,
    float* __restrict__ proj)
{
    __shared__ float As[16][96];   // v3 [k][d]
    __shared__ float Bs[16][128];  // e  [k][s]
    const int nh = blockIdx.z, n = nh >> 3, h = nh & 7;
    const float* V = g_v3 + (size_t)n * CC * LL + (size_t)h * DD * LL;
    float* pr = proj + (size_t)nh * SS * LL;
    const int n0 = blockIdx.x * 128;
    const int tid = threadIdx.x, ty = tid >> 4, tx = tid & 15;
    const float* tmn = tmask + (size_t)n * LL;

    float acc[6][8];
#pragma unroll
    for (int i = 0; i < 6; i++)
#pragma unroll
        for (int j = 0; j < 8; j++) acc[i][j] = 0.f;

    for (int k0 = 0; k0 < LL; k0 += 16) {
        if (tid < 128) {                        // v3 tile: 96 x 16, transpose
#pragma unroll
            for (int t = 0; t < 3; t++) {
                int idx = tid + t * 128;
                int row = idx >> 2, c4 = idx & 3;
                float4 a = *(const float4*)(V + (size_t)row * LL + k0 + c4 * 4);
                As[c4*4+0][row] = a.x; As[c4*4+1][row] = a.y;
                As[c4*4+2][row] = a.z; As[c4*4+3][row] = a.w;
            }
        }
#pragma unroll
        for (int t = 0; t < 2; t++) {           // coef tile: 128 s x 16 l; exp into Bs, mask-writeback
            int idx = tid + t * 256;
            int row = idx >> 2, c4 = idx & 3;
            int l = k0 + c4 * 4;
            size_t gi = (size_t)(n0 + row) * LL + l;
            float4 c = *(float4*)(pr + gi);
            Bs[c4*4+0][row] = expf(c.x);
            Bs[c4*4+1][row] = expf(c.y);
            Bs[c4*4+2][row] = expf(c.z);
            Bs[c4*4+3][row] = expf(c.w);
            float4 tm4 = *(const float4*)(tmn + l);
            c.x *= tm4.x; c.y *= tm4.y; c.z *= tm4.z; c.w *= tm4.w;
            *(float4*)(pr + gi) = c;            // final proj output: coef * tm
        }
        __syncthreads();
#pragma unroll
        for (int kk = 0; kk < 16; kk++) {
            float a[6], b[8];
#pragma unroll
            for (int i = 0; i < 6; i++) a[i] = As[kk][ty*6 + i];
            *(float4*)&b[0] = *(float4*)&Bs[kk][tx*8];
            *(float4*)&b[4] = *(float4*)&Bs[kk][tx*8+4];
#pragma unroll
            for (int i = 0; i < 6; i++)
#pragma unroll
                for (int j = 0; j < 8; j++)
                    acc[i][j] += a[i] * b[j];
        }
        __syncthreads();
    }

    float dv[8];
#pragma unroll
    for (int j = 0; j < 8; j++)
        dv[j] = 1.f / (g_denom[(size_t)nh * SS + n0 + tx*8 + j] + 1e-6f);
#pragma unroll
    for (int i = 0; i < 6; i++) {
        int d = ty*6 + i, o = h * DD + d;
        size_t base = (size_t)n * CC * SS + (size_t)o * SS + n0 + tx*8;
        float4 x0 = *(const float4*)(x + base);
        float4 x1 = *(const float4*)(x + base + 4);
        float4 r0 = make_float4(x0.x + acc[i][0]*dv[0], x0.y + acc[i][1]*dv[1],
                                x0.z + acc[i][2]*dv[2], x0.w + acc[i][3]*dv[3]);
        float4 r1 = make_float4(x1.x + acc[i][4]*dv[4], x1.y + acc[i][5]*dv[5],
                                x1.z + acc[i][6]*dv[6], x1.w + acc[i][7]*dv[7]);
        *(float4*)(g_y + base)     = r0;
        *(float4*)(g_y + base + 4) = r1;
    }
}

extern "C" void kernel_launch(void* const* d_in, const int* in_sizes, int n_in,
                              void* d_out, int out_size)
{
    const float* x     = (const float*)d_in[0];
    const float* xt    = (const float*)d_in[1];
    const float* tmask = (const float*)d_in[2];
    const float* im    = (const float*)d_in[3];
    const float* Wv    = (const float*)d_in[4];
    const float* Wk    = (const float*)d_in[5];
    const float* Wq    = (const float*)d_in[6];
    const float* W1    = (const float*)d_in[7];
    const float* W2    = (const float*)d_in[8];
    float* outx = (float*)d_out;
    float* proj = outx + (size_t)NB * CC * SS;

    float *pv3, *pk, *pq, *py, *ph;
    cudaGetSymbolAddress((void**)&pv3, g_v3);
    cudaGetSymbolAddress((void**)&pk,  g_k);
    cudaGetSymbolAddress((void**)&pq,  g_q);
    cudaGetSymbolAddress((void**)&py,  g_y);
    cudaGetSymbolAddress((void**)&ph,  g_h);

    zero_denom_kernel<<<(NH*SS + 1023)/1024, 1024>>>();

    // v3 = (Wv @ x_t) * tm^3        (M=768, N=1024, K=384)
    gemm_nn_kernel<EPI_V3><<<dim3(LL/128, CC/128, NB), 256>>>(Wv, xt, pv3, CC, LL, TCH, tmask);
    // k = Wk @ x_t
    gemm_nn_kernel<EPI_NONE><<<dim3(LL/128, CC/128, NB), 256>>>(Wk, xt, pk, CC, LL, TCH, nullptr);
    // q = Wq @ x                    (M=768, N=4096, K=768)
    gemm_nn_kernel<EPI_NONE><<<dim3(SS/128, CC/128, NB), 256>>>(Wq, x, pq, CC, SS, CC, nullptr);

    // coef + denom                  per (n,h): 4096 x 1024 x 96
    coef_kernel<<<dim3(LL/128, SS/128, NH), 256>>>(im, tmask, proj);

    // x_p, y = x + x_p; finalize proj output
    xp_kernel<<<dim3(SS/128, 1, NH), 256>>>(x, tmask, proj);

    // hmid = relu(W1 @ y)           (M=1536, N=4096, K=768)
    gemm_nn_kernel<EPI_RELU><<<dim3(SS/128, FF/128, NB), 256>>>(W1, py, ph, FF, SS, CC, nullptr);
    // out_x = x + W2 @ hmid         (M=768, N=4096, K=1536)
    gemm_nn_kernel<EPI_ADDX><<<dim3(SS/128, CC/128, NB), 256>>>(W2, ph, outx, CC, SS, FF, x);
}

// round 3
// speedup vs baseline: 1.9114x; 1.9114x over previous
#include <cuda_runtime.h>
#include <math.h>
#include <stdint.h>

// ---- arch-feature gate: tcgen05 only exists in the sm_103a/sm_100a passes ----
#if defined(__CUDA_ARCH_FEAT_SM103_ALL) || defined(__CUDA_ARCH_FEAT_SM100_ALL) || defined(__CUDA_ARCH_FEAT_SM101_ALL)
#  define HAS_TC 1
#elif defined(__CUDA_ARCH_HAS_FEATURE__)
#  if __CUDA_ARCH_HAS_FEATURE__(SM103_ALL) || __CUDA_ARCH_HAS_FEATURE__(SM100_ALL)
#    define HAS_TC 1
#  else
#    define HAS_TC 0
#  endif
#else
#  define HAS_TC 0
#endif

#define NBATCH 2
#define C_DIM  768
#define S_DIM  4096
#define L_DIM  1024
#define D_DIM  96
#define T_DIM  384
#define F_DIM  1536
#define NHEAD  16

// ------------- scratch (__device__ globals; no allocation allowed) -------------
static __device__ float g_xT [NBATCH*S_DIM*C_DIM];   // x transposed  [n][s][c]
static __device__ float g_xtT[NBATCH*L_DIM*T_DIM];   // x_t transposed [n][l][tc]
static __device__ float g_qt [NBATCH*S_DIM*C_DIM];   // q_t [n][s][c]
static __device__ float g_kt [NBATCH*L_DIM*C_DIM];   // k_t [n][l][c]
static __device__ float g_v3 [NBATCH*C_DIM*L_DIM];   // v*tm^3 [n][c][l]
static __device__ float g_yt [NBATCH*S_DIM*C_DIM];   // y transposed [n][s][c]
static __device__ float g_ht [NBATCH*S_DIM*F_DIM];   // relu(W1 y) [n][s][f]
static __device__ float g_dn [NHEAD*S_DIM];          // softmax denominators

// ---------------------------- PTX helpers ----------------------------
__device__ __forceinline__ uint32_t smem_u32(const void* p){
    uint32_t a;
    asm("{ .reg .u64 t; cvta.to.shared.u64 t, %1; cvt.u32.u64 %0, t; }":"=r"(a):"l"(p));
    return a;
}
__device__ __forceinline__ uint32_t elect_one(){
    uint32_t r;
    asm volatile("{\n\t.reg .pred p;\n\telect.sync _|p, 0xFFFFFFFF;\n\tselp.b32 %0, 1, 0, p;\n\t}":"=r"(r));
    return r;
}
__device__ __forceinline__ float to_tf32(float x){
    uint32_t u; asm("cvt.rna.tf32.f32 %0, %1;":"=r"(u):"f"(x));
    return __uint_as_float(u);
}
#define SWZ(o) ((o) ^ ((((uint32_t)(o))>>3)&0x70u))

__device__ __forceinline__ void mbar_init(uint32_t a, uint32_t cnt){
    asm volatile("mbarrier.init.shared.b64 [%0], %1;"::"r"(a),"r"(cnt):"memory");
}
__device__ __forceinline__ void mbar_wait(uint32_t a, uint32_t ph){
    asm volatile(
        "{\n\t.reg .pred P;\n\t"
        "WL%=:\n\t"
        "mbarrier.try_wait.parity.acquire.cta.shared::cta.b64 P, [%0], %1;\n\t"
        "@P bra WD%=;\n\t"
        "bra WL%=;\n\t"
        "WD%=:\n\t}"
        ::"r"(a),"r"(ph):"memory");
}
__device__ __forceinline__ void tc_commit(uint32_t mb){
#if HAS_TC
    asm volatile("tcgen05.commit.cta_group::1.mbarrier::arrive::one.shared::cluster.b64 [%0];"
                 ::"r"(mb):"memory");
#endif
}
__device__ __forceinline__ void tc_alloc(uint32_t smem_dst, uint32_t ncols){
#if HAS_TC
    asm volatile("tcgen05.alloc.cta_group::1.sync.aligned.shared::cta.b32 [%0], %1;"
                 ::"r"(smem_dst),"r"(ncols):"memory");
#endif
}
__device__ __forceinline__ void tc_dealloc(uint32_t tmem, uint32_t ncols){
#if HAS_TC
    asm volatile("tcgen05.dealloc.cta_group::1.sync.aligned.b32 %0, %1;"::"r"(tmem),"r"(ncols));
#endif
}
__device__ __forceinline__ void tc_relinquish(){
#if HAS_TC
    asm volatile("tcgen05.relinquish_alloc_permit.cta_group::1.sync.aligned;");
#endif
}
__device__ __forceinline__ void fence_after(){
#if HAS_TC
    asm volatile("tcgen05.fence::after_thread_sync;":::"memory");
#endif
}
__device__ __forceinline__ void fence_proxy(){
    asm volatile("fence.proxy.async.shared::cta;":::"memory");
}
__device__ __forceinline__ void tc_wait_ld(){
#if HAS_TC
    asm volatile("tcgen05.wait::ld.sync.aligned;":::"memory");
#endif
}
__device__ __forceinline__ uint64_t mk_desc(uint32_t addr){
    const uint64_t BASE = (uint64_t(2)<<61)|(uint64_t(1)<<46)|(uint64_t(64)<<32)|(uint64_t(1)<<16);
    return BASE | ((uint64_t)(addr>>4) & 0x3FFFull);
}
__device__ __forceinline__ void mma_tf32(uint32_t d, uint64_t ad, uint64_t bd, uint32_t idesc, uint32_t en){
#if HAS_TC
    asm volatile(
        "{\n\t.reg .pred p;\n\tsetp.ne.u32 p, %5, 0;\n\t"
        "tcgen05.mma.cta_group::1.kind::tf32 [%0], %1, %2, %3, {%4,%4,%4,%4}, p;\n\t}"
        :: "r"(d), "l"(ad), "l"(bd), "r"(idesc), "r"(0u), "r"(en) : "memory");
#endif
}
#if HAS_TC
#define LDTM32(r, a) \
    asm volatile( \
        "tcgen05.ld.sync.aligned.32x32b.x32.b32 " \
        "{%0, %1, %2, %3, %4, %5, %6, %7, " \
        " %8, %9, %10, %11, %12, %13, %14, %15, " \
        " %16, %17, %18, %19, %20, %21, %22, %23, " \
        " %24, %25, %26, %27, %28, %29, %30, %31}, [%32];" \
        : "=r"((r)[0]),  "=r"((r)[1]),  "=r"((r)[2]),  "=r"((r)[3]), \
          "=r"((r)[4]),  "=r"((r)[5]),  "=r"((r)[6]),  "=r"((r)[7]), \
          "=r"((r)[8]),  "=r"((r)[9]),  "=r"((r)[10]), "=r"((r)[11]), \
          "=r"((r)[12]), "=r"((r)[13]), "=r"((r)[14]), "=r"((r)[15]), \
          "=r"((r)[16]), "=r"((r)[17]), "=r"((r)[18]), "=r"((r)[19]), \
          "=r"((r)[20]), "=r"((r)[21]), "=r"((r)[22]), "=r"((r)[23]), \
          "=r"((r)[24]), "=r"((r)[25]), "=r"((r)[26]), "=r"((r)[27]), \
          "=r"((r)[28]), "=r"((r)[29]), "=r"((r)[30]), "=r"((r)[31]) \
        : "r"(a))
#endif

// ---------------------------- small kernels ----------------------------
__global__ void zero_denom_kernel(){
    int i = blockIdx.x*blockDim.x + threadIdx.x;
    if (i < NHEAD*S_DIM) g_dn[i] = 0.f;
}
// src [R][Cc] -> dst [Cc][R], per batch slice
__global__ void transpose_kernel(const float* __restrict__ src, float* __restrict__ dst,
                                 int R, int Cc){
    __shared__ float t[32][33];
    int nb = blockIdx.z;
    src += (size_t)nb*R*Cc;  dst += (size_t)nb*R*Cc;
    int c0 = blockIdx.x*32, r0 = blockIdx.y*32;
    int x = threadIdx.x, y = threadIdx.y;
#pragma unroll
    for (int i = 0; i < 32; i += 8)
        t[y+i][x] = src[(size_t)(r0+y+i)*Cc + c0 + x];
    __syncthreads();
#pragma unroll
    for (int i = 0; i < 32; i += 8)
        dst[(size_t)(c0+y+i)*R + r0 + x] = t[x][y+i];
}

// ---------------------------- tcgen05 tf32 GEMM ----------------------------
#define SM_TMEM 0
#define SM_MB   16
#define SM_A(b) (1024u  + (uint32_t)(b)*16384u)
#define SM_B(b) (33792u + (uint32_t)(b)*16384u)
#define SMEM_BYTES 66560

struct GP {
    const float* A; const float* B; float* C;
    const float* tm; const float* im; const float* xa;
    float* dn; float* pj;
};

// Fill a K-major SW128 tile: rows x 32 floats (128B/row), tf32-rounded.
__device__ __forceinline__ void fill_tile(const float* __restrict__ src, int ld, int rows,
                                          char* smem, uint32_t base, int tid){
    int total = rows * 8;
    for (int idx = tid; idx < total; idx += 256){
        int row = idx >> 3, c4 = idx & 7;
        float4 v = *(const float4*)(src + (size_t)row*ld + c4*4);
        v.x = to_tf32(v.x); v.y = to_tf32(v.y); v.z = to_tf32(v.z); v.w = to_tf32(v.w);
        *(float4*)(smem + base + SWZ((uint32_t)row*128u + (uint32_t)c4*16u)) = v;
    }
}

template<int MODE>
__global__ void __launch_bounds__(256)
tc_gemm(GP g)
{
    extern __shared__ char smem[];
    uint32_t sb = smem_u32(smem);
    const int tid = threadIdx.x, wid = tid >> 5, lid = tid & 31;
    const int m0 = blockIdx.y*128, n0 = blockIdx.x*128, bz = blockIdx.z;
    int nb, hh = 0;
    if constexpr (MODE==3 || MODE==4) { nb = bz >> 3; hh = bz & 7; } else { nb = bz; }

    constexpr int NCOL = (MODE==4) ? 96 : 128;
    constexpr int KK   = (MODE==0||MODE==1) ? T_DIM :
                         (MODE==2||MODE==5) ? C_DIM :
                         (MODE==3) ? D_DIM :
                         (MODE==4) ? L_DIM : F_DIM;
    constexpr int NT = KK / 32;
    constexpr uint32_t IDESC = (1u<<4)|(2u<<7)|(2u<<10)|((uint32_t)(NCOL/8)<<17)|(8u<<24);

    const float* Ap = nullptr; const float* Bp = nullptr; float* Cbase = nullptr;
    int ldA = 0, ldB = 0, ldC = 0;
    if constexpr (MODE==0){ Ap=g.A+(size_t)nb*L_DIM*T_DIM+(size_t)m0*T_DIM; ldA=T_DIM;
                            Bp=g.B+(size_t)n0*T_DIM; ldB=T_DIM;
                            Cbase=g.C+(size_t)nb*L_DIM*C_DIM+(size_t)m0*C_DIM+n0; ldC=C_DIM; }
    if constexpr (MODE==1){ Ap=g.A+(size_t)m0*T_DIM; ldA=T_DIM;
                            Bp=g.B+(size_t)nb*L_DIM*T_DIM+(size_t)n0*T_DIM; ldB=T_DIM;
                            Cbase=g.C+(size_t)nb*C_DIM*L_DIM+(size_t)m0*L_DIM+n0; ldC=L_DIM; }
    if constexpr (MODE==2){ Ap=g.A+(size_t)nb*S_DIM*C_DIM+(size_t)m0*C_DIM; ldA=C_DIM;
                            Bp=g.B+(size_t)n0*C_DIM; ldB=C_DIM;
                            Cbase=g.C+(size_t)nb*S_DIM*C_DIM+(size_t)m0*C_DIM+n0; ldC=C_DIM; }
    if constexpr (MODE==3){ Ap=g.A+(size_t)nb*S_DIM*C_DIM+(size_t)m0*C_DIM+hh*D_DIM; ldA=C_DIM;
                            Bp=g.B+(size_t)nb*L_DIM*C_DIM+(size_t)n0*C_DIM+hh*D_DIM; ldB=C_DIM;
                            Cbase=g.C+(size_t)bz*S_DIM*L_DIM+(size_t)m0*L_DIM+n0; ldC=L_DIM; }
    if constexpr (MODE==4){ Bp=g.B+(size_t)nb*C_DIM*L_DIM+(size_t)hh*D_DIM*L_DIM; ldB=L_DIM;
                            Cbase=g.C+(size_t)nb*S_DIM*C_DIM+(size_t)m0*C_DIM+hh*D_DIM; ldC=C_DIM; }
    if constexpr (MODE==5){ Ap=g.A+(size_t)nb*S_DIM*C_DIM+(size_t)m0*C_DIM; ldA=C_DIM;
                            Bp=g.B+(size_t)n0*C_DIM; ldB=C_DIM;
                            Cbase=g.C+(size_t)nb*S_DIM*F_DIM+(size_t)m0*F_DIM+n0; ldC=F_DIM; }
    if constexpr (MODE==6){ Ap=g.A+(size_t)m0*F_DIM; ldA=F_DIM;
                            Bp=g.B+(size_t)nb*S_DIM*F_DIM+(size_t)n0*F_DIM; ldB=F_DIM;
                            Cbase=g.C+(size_t)nb*C_DIM*S_DIM+(size_t)m0*S_DIM+n0; ldC=S_DIM; }

    float* Pj = nullptr; const float* tmn = nullptr;
    if constexpr (MODE==4){
        Pj  = g.pj + (size_t)bz*S_DIM*L_DIM + (size_t)m0*L_DIM;
        tmn = g.tm + (size_t)nb*L_DIM;
    }

#if HAS_TC
    if (wid == 0) tc_alloc(sb + SM_TMEM, 128);
    if (tid == 0){ mbar_init(sb + SM_MB, 1); mbar_init(sb + SM_MB + 16, 1); }
    __syncthreads();
    uint32_t tmem;
    asm volatile("ld.shared.b32 %0, [%1];" : "=r"(tmem) : "r"(sb + SM_TMEM));
    if (wid == 0) tc_relinquish();
    int ph0 = 0, ph1 = 0;
#else
    float facc[NCOL];
#pragma unroll
    for (int j = 0; j < NCOL; j++) facc[j] = 0.f;
#endif

    for (int t = 0; t < NT; t++){
        const int b = t & 1;
        const uint32_t mb = sb + SM_MB + (uint32_t)b*16u;
#if HAS_TC
        if (t >= 2){
            if (b == 0){ mbar_wait(mb, (uint32_t)ph0); ph0 ^= 1; }
            else       { mbar_wait(mb, (uint32_t)ph1); ph1 ^= 1; }
        }
#else
        (void)mb;
#endif
        // ---- fill A stage ----
        if constexpr (MODE==4){
            const int k0 = t*32;
            for (int idx = tid; idx < 1024; idx += 256){
                int row = idx >> 3, c4 = idx & 7;
                size_t go = (size_t)row*L_DIM + k0 + c4*4;
                float4 c = *(float4*)(Pj + go);
                float4 e;
                e.x = to_tf32(expf(c.x)); e.y = to_tf32(expf(c.y));
                e.z = to_tf32(expf(c.z)); e.w = to_tf32(expf(c.w));
                *(float4*)(smem + SM_A(b) + SWZ((uint32_t)row*128u + (uint32_t)c4*16u)) = e;
                float4 t4 = *(const float4*)(tmn + k0 + c4*4);
                c.x *= t4.x; c.y *= t4.y; c.z *= t4.z; c.w *= t4.w;
                *(float4*)(Pj + go) = c;   // final proj output: coef * tm
            }
        } else {
            fill_tile(Ap + t*32, ldA, 128, smem, SM_A(b), tid);
        }
        // ---- fill B stage ----
        fill_tile(Bp + t*32, ldB, NCOL, smem, SM_B(b), tid);
        __syncthreads();
#if HAS_TC
        if (wid == 0 && elect_one()){
            fence_proxy();
            uint64_t ad = mk_desc(sb + SM_A(b));
            uint64_t bd = mk_desc(sb + SM_B(b));
#pragma unroll
            for (int c = 0; c < 4; c++)
                mma_tf32(tmem, ad + c*2, bd + c*2, IDESC, (t > 0 || c > 0) ? 1u : 0u);
            tc_commit(mb);
        }
#else
        // SIMT fallback: thread tid<128 owns output row tid
        if (tid < 128){
            for (int kk = 0; kk < 32; kk++){
                float a = *(const float*)(smem + SM_A(b) + SWZ((uint32_t)tid*128u + (uint32_t)kk*4u));
#pragma unroll
                for (int j = 0; j < NCOL; j++)
                    facc[j] += a * *(const float*)(smem + SM_B(b) + SWZ((uint32_t)j*128u + (uint32_t)kk*4u));
            }
        }
        __syncthreads();
#endif
    }
#if HAS_TC
    {   // wait for the last tile's MMAs
        const int bl = (NT - 1) & 1;
        mbar_wait(sb + SM_MB + (uint32_t)bl*16u, (uint32_t)(bl ? ph1 : ph0));
    }
    fence_after();
#endif

    // ---------------- epilogue: warps 0-3 handle rows ----------------
    if (wid < 4){
        const int m = wid*32 + lid;
        float* Crow = Cbase + (size_t)m*ldC;
        float scl = 0.f, dv = 0.f, rsum = 0.f;
        const float* tmb = nullptr; const float* Xrow = nullptr;
        if constexpr (MODE==1) tmb = g.tm + (size_t)nb*L_DIM + n0;
        if constexpr (MODE==3){
            scl = g.im[(size_t)nb*S_DIM + m0 + m] * 0.1020620726159657f;
            tmb = g.tm + (size_t)nb*L_DIM + n0;
        }
        if constexpr (MODE==4){
            dv   = 1.f / (g.dn[(size_t)bz*S_DIM + m0 + m] + 1e-6f);
            Xrow = g.xa + (size_t)nb*S_DIM*C_DIM + (size_t)(m0 + m)*C_DIM + hh*D_DIM;
        }
        if constexpr (MODE==6)
            Xrow = g.xa + (size_t)nb*C_DIM*S_DIM + (size_t)(m0 + m)*S_DIM + n0;

#pragma unroll
        for (int ch = 0; ch < NCOL/32; ch++){
            float v[32];
#if HAS_TC
            uint32_t r[32];
            LDTM32(r, tmem + (uint32_t)ch*32u);
            tc_wait_ld();
#pragma unroll
            for (int j = 0; j < 32; j++) v[j] = __uint_as_float(r[j]);
#else
#pragma unroll
            for (int j = 0; j < 32; j++) v[j] = facc[ch*32 + j];
#endif
            if constexpr (MODE==1){
#pragma unroll
                for (int j = 0; j < 32; j++){ float tt = tmb[ch*32 + j]; v[j] *= tt*tt*tt; }
            }
            if constexpr (MODE==3){
#pragma unroll
                for (int j = 0; j < 32; j++){
                    v[j] *= scl;
                    rsum += expf(v[j]) * tmb[ch*32 + j];
                }
            }
            if constexpr (MODE==4){
#pragma unroll
                for (int j = 0; j < 32; j++) v[j] = v[j]*dv + Xrow[ch*32 + j];
            }
            if constexpr (MODE==5){
#pragma unroll
                for (int j = 0; j < 32; j++) v[j] = fmaxf(v[j], 0.f);
            }
            if constexpr (MODE==6){
#pragma unroll
                for (int j4 = 0; j4 < 8; j4++){
                    float4 xv = *(const float4*)(Xrow + ch*32 + j4*4);
                    v[j4*4+0] += xv.x; v[j4*4+1] += xv.y; v[j4*4+2] += xv.z; v[j4*4+3] += xv.w;
                }
            }
#pragma unroll
            for (int j4 = 0; j4 < 8; j4++)
                *(float4*)(Crow + ch*32 + j4*4) =
                    make_float4(v[j4*4], v[j4*4+1], v[j4*4+2], v[j4*4+3]);
        }
        if constexpr (MODE==3)
            atomicAdd(g.dn + (size_t)bz*S_DIM + m0 + m, rsum);
    }
#if HAS_TC
    __syncthreads();
    if (wid == 0) tc_dealloc(tmem, 128);
#endif
}

// ---------------------------- host ----------------------------
extern "C" void kernel_launch(void* const* d_in, const int* in_sizes, int n_in,
                              void* d_out, int out_size)
{
    const float* x     = (const float*)d_in[0];
    const float* xt    = (const float*)d_in[1];
    const float* tmask = (const float*)d_in[2];
    const float* im    = (const float*)d_in[3];
    const float* Wv    = (const float*)d_in[4];
    const float* Wk    = (const float*)d_in[5];
    const float* Wq    = (const float*)d_in[6];
    const float* W1    = (const float*)d_in[7];
    const float* W2    = (const float*)d_in[8];
    float* outx = (float*)d_out;
    float* proj = outx + (size_t)NBATCH*C_DIM*S_DIM;

    float *pxT, *pxtT, *pqt, *pkt, *pv3, *pyt, *pht, *pdn;
    cudaGetSymbolAddress((void**)&pxT,  g_xT);
    cudaGetSymbolAddress((void**)&pxtT, g_xtT);
    cudaGetSymbolAddress((void**)&pqt,  g_qt);
    cudaGetSymbolAddress((void**)&pkt,  g_kt);
    cudaGetSymbolAddress((void**)&pv3,  g_v3);
    cudaGetSymbolAddress((void**)&pyt,  g_yt);
    cudaGetSymbolAddress((void**)&pht,  g_ht);
    cudaGetSymbolAddress((void**)&pdn,  g_dn);

    cudaFuncSetAttribute((const void*)tc_gemm<0>, cudaFuncAttributeMaxDynamicSharedMemorySize, SMEM_BYTES);
    cudaFuncSetAttribute((const void*)tc_gemm<1>, cudaFuncAttributeMaxDynamicSharedMemorySize, SMEM_BYTES);
    cudaFuncSetAttribute((const void*)tc_gemm<2>, cudaFuncAttributeMaxDynamicSharedMemorySize, SMEM_BYTES);
    cudaFuncSetAttribute((const void*)tc_gemm<3>, cudaFuncAttributeMaxDynamicSharedMemorySize, SMEM_BYTES);
    cudaFuncSetAttribute((const void*)tc_gemm<4>, cudaFuncAttributeMaxDynamicSharedMemorySize, SMEM_BYTES);
    cudaFuncSetAttribute((const void*)tc_gemm<5>, cudaFuncAttributeMaxDynamicSharedMemorySize, SMEM_BYTES);
    cudaFuncSetAttribute((const void*)tc_gemm<6>, cudaFuncAttributeMaxDynamicSharedMemorySize, SMEM_BYTES);

    dim3 tb(32, 8);
    transpose_kernel<<<dim3(S_DIM/32, C_DIM/32, NBATCH), tb>>>(x,  pxT,  C_DIM, S_DIM);
    transpose_kernel<<<dim3(L_DIM/32, T_DIM/32, NBATCH), tb>>>(xt, pxtT, T_DIM, L_DIM);
    zero_denom_kernel<<<(NHEAD*S_DIM + 255)/256, 256>>>();

    GP g;

    // k_t[l][c] = xtT . Wk^T
    g = {pxtT, Wk, pkt, nullptr, nullptr, nullptr, nullptr, nullptr};
    tc_gemm<0><<<dim3(C_DIM/128, L_DIM/128, NBATCH), 256, SMEM_BYTES>>>(g);
    // v3[c][l] = (Wv . xtT^T) * tm^3
    g = {Wv, pxtT, pv3, tmask, nullptr, nullptr, nullptr, nullptr};
    tc_gemm<1><<<dim3(L_DIM/128, C_DIM/128, NBATCH), 256, SMEM_BYTES>>>(g);
    // q_t[s][c] = xT . Wq^T
    g = {pxT, Wq, pqt, nullptr, nullptr, nullptr, nullptr, nullptr};
    tc_gemm<2><<<dim3(C_DIM/128, S_DIM/128, NBATCH), 256, SMEM_BYTES>>>(g);
    // coef[s][l] per head (+denom)
    g = {pqt, pkt, proj, tmask, im, nullptr, pdn, nullptr};
    tc_gemm<3><<<dim3(L_DIM/128, S_DIM/128, NHEAD), 256, SMEM_BYTES>>>(g);
    // xp -> y_t ; proj finalized to coef*tm
    g = {nullptr, pv3, pyt, tmask, nullptr, pxT, pdn, proj};
    tc_gemm<4><<<dim3(1, S_DIM/128, NHEAD), 256, SMEM_BYTES>>>(g);
    // hmid = relu(y_t . W1^T)
    g = {pyt, W1, pht, nullptr, nullptr, nullptr, nullptr, nullptr};
    tc_gemm<5><<<dim3(F_DIM/128, S_DIM/128, NBATCH), 256, SMEM_BYTES>>>(g);
    // out[c][s] = x + W2 . h_t^T
    g = {W2, pht, outx, nullptr, nullptr, x, nullptr, nullptr};
    tc_gemm<6><<<dim3(S_DIM/128, C_DIM/128, NBATCH), 256, SMEM_BYTES>>>(g);
}

// round 4
// speedup vs baseline: 3.3192x; 1.7365x over previous
#include <cuda_runtime.h>
#include <math.h>
#include <stdint.h>

// ---- arch-feature gate: tcgen05 only exists in the sm_103a/sm_100a passes ----
#if defined(__CUDA_ARCH_FEAT_SM103_ALL) || defined(__CUDA_ARCH_FEAT_SM100_ALL) || defined(__CUDA_ARCH_FEAT_SM101_ALL)
#  define HAS_TC 1
#elif defined(__CUDA_ARCH_HAS_FEATURE__)
#  if __CUDA_ARCH_HAS_FEATURE__(SM103_ALL) || __CUDA_ARCH_HAS_FEATURE__(SM100_ALL)
#    define HAS_TC 1
#  else
#    define HAS_TC 0
#  endif
#else
#  define HAS_TC 0
#endif

#define NBATCH 2
#define C_DIM  768
#define S_DIM  4096
#define L_DIM  1024
#define D_DIM  96
#define T_DIM  384
#define F_DIM  1536
#define NHEAD  16

// ------------- scratch (__device__ globals; no allocation allowed) -------------
static __device__ float g_xTr[NBATCH*S_DIM*C_DIM];   // x^T raw   [n][s][c]
static __device__ float g_xT [NBATCH*S_DIM*C_DIM];   // x^T tf32  [n][s][c]
static __device__ float g_xtT[NBATCH*L_DIM*T_DIM];   // x_t^T tf32 [n][l][tc]
static __device__ float g_qt [NBATCH*S_DIM*C_DIM];   // q_t tf32
static __device__ float g_kt [NBATCH*L_DIM*C_DIM];   // k_t tf32
static __device__ float g_v3 [NBATCH*C_DIM*L_DIM];   // v*tm^3 tf32
static __device__ float g_yt [NBATCH*S_DIM*C_DIM];   // y^T tf32
static __device__ float g_ht [NBATCH*S_DIM*F_DIM];   // relu(W1 y) tf32
static __device__ float g_dn [NHEAD*S_DIM];          // softmax denominators
// tf32 copies of weights, concatenated
#define WV_OFF 0
#define WK_OFF (C_DIM*T_DIM)
#define WQ_OFF (2*C_DIM*T_DIM)
#define W1_OFF (2*C_DIM*T_DIM + C_DIM*C_DIM)
#define W2_OFF (W1_OFF + 2*C_DIM*C_DIM)
#define W_TOT  (W2_OFF + 2*C_DIM*C_DIM)
static __device__ float g_w32[W_TOT];

// ---------------------------- PTX helpers ----------------------------
__device__ __forceinline__ uint32_t smem_u32(const void* p){
    uint32_t a;
    asm("{ .reg .u64 t; cvta.to.shared.u64 t, %1; cvt.u32.u64 %0, t; }":"=r"(a):"l"(p));
    return a;
}
__device__ __forceinline__ uint32_t elect_one(){
    uint32_t r;
    asm volatile("{\n\t.reg .pred p;\n\telect.sync _|p, 0xFFFFFFFF;\n\tselp.b32 %0, 1, 0, p;\n\t}":"=r"(r));
    return r;
}
__device__ __forceinline__ float to_tf32(float x){
    uint32_t u; asm("cvt.rna.tf32.f32 %0, %1;":"=r"(u):"f"(x));
    return __uint_as_float(u);
}
#define SWZ(o) ((o) ^ ((((uint32_t)(o))>>3)&0x70u))

__device__ __forceinline__ void cp16(uint32_t dst, const void* src){
    asm volatile("cp.async.cg.shared.global [%0], [%1], 16;"::"r"(dst),"l"(src):"memory");
}
__device__ __forceinline__ void cp_commit(){
    asm volatile("cp.async.commit_group;":::"memory");
}
template<int N> __device__ __forceinline__ void cp_wait(){
    asm volatile("cp.async.wait_group %0;"::"n"(N):"memory");
}
__device__ __forceinline__ void mbar_init(uint32_t a, uint32_t cnt){
    asm volatile("mbarrier.init.shared.b64 [%0], %1;"::"r"(a),"r"(cnt):"memory");
}
__device__ __forceinline__ void mbar_wait(uint32_t a, uint32_t ph){
    asm volatile(
        "{\n\t.reg .pred P;\n\t"
        "WL%=:\n\t"
        "mbarrier.try_wait.parity.acquire.cta.shared::cta.b64 P, [%0], %1;\n\t"
        "@P bra WD%=;\n\t"
        "bra WL%=;\n\t"
        "WD%=:\n\t}"
        ::"r"(a),"r"(ph):"memory");
}
__device__ __forceinline__ void tc_commit(uint32_t mb){
#if HAS_TC
    asm volatile("tcgen05.commit.cta_group::1.mbarrier::arrive::one.shared::cluster.b64 [%0];"
                 ::"r"(mb):"memory");
#endif
}
__device__ __forceinline__ void tc_alloc(uint32_t smem_dst, uint32_t ncols){
#if HAS_TC
    asm volatile("tcgen05.alloc.cta_group::1.sync.aligned.shared::cta.b32 [%0], %1;"
                 ::"r"(smem_dst),"r"(ncols):"memory");
#endif
}
__device__ __forceinline__ void tc_dealloc(uint32_t tmem, uint32_t ncols){
#if HAS_TC
    asm volatile("tcgen05.dealloc.cta_group::1.sync.aligned.b32 %0, %1;"::"r"(tmem),"r"(ncols));
#endif
}
__device__ __forceinline__ void tc_relinquish(){
#if HAS_TC
    asm volatile("tcgen05.relinquish_alloc_permit.cta_group::1.sync.aligned;");
#endif
}
__device__ __forceinline__ void fence_after(){
#if HAS_TC
    asm volatile("tcgen05.fence::after_thread_sync;":::"memory");
#endif
}
__device__ __forceinline__ void fence_proxy(){
    asm volatile("fence.proxy.async.shared::cta;":::"memory");
}
__device__ __forceinline__ void tc_wait_ld(){
#if HAS_TC
    asm volatile("tcgen05.wait::ld.sync.aligned;":::"memory");
#endif
}
__device__ __forceinline__ uint64_t mk_desc(uint32_t addr){
    const uint64_t BASE = (uint64_t(2)<<61)|(uint64_t(1)<<46)|(uint64_t(64)<<32)|(uint64_t(1)<<16);
    return BASE | ((uint64_t)(addr>>4) & 0x3FFFull);
}
__device__ __forceinline__ void mma_tf32(uint32_t d, uint64_t ad, uint64_t bd, uint32_t idesc, uint32_t en){
#if HAS_TC
    asm volatile(
        "{\n\t.reg .pred p;\n\tsetp.ne.u32 p, %5, 0;\n\t"
        "tcgen05.mma.cta_group::1.kind::tf32 [%0], %1, %2, %3, {%4,%4,%4,%4}, p;\n\t}"
        :: "r"(d), "l"(ad), "l"(bd), "r"(idesc), "r"(0u), "r"(en) : "memory");
#endif
}
#if HAS_TC
#define LDTM32(r, a) \
    asm volatile( \
        "tcgen05.ld.sync.aligned.32x32b.x32.b32 " \
        "{%0, %1, %2, %3, %4, %5, %6, %7, " \
        " %8, %9, %10, %11, %12, %13, %14, %15, " \
        " %16, %17, %18, %19, %20, %21, %22, %23, " \
        " %24, %25, %26, %27, %28, %29, %30, %31}, [%32];" \
        : "=r"((r)[0]),  "=r"((r)[1]),  "=r"((r)[2]),  "=r"((r)[3]), \
          "=r"((r)[4]),  "=r"((r)[5]),  "=r"((r)[6]),  "=r"((r)[7]), \
          "=r"((r)[8]),  "=r"((r)[9]),  "=r"((r)[10]), "=r"((r)[11]), \
          "=r"((r)[12]), "=r"((r)[13]), "=r"((r)[14]), "=r"((r)[15]), \
          "=r"((r)[16]), "=r"((r)[17]), "=r"((r)[18]), "=r"((r)[19]), \
          "=r"((r)[20]), "=r"((r)[21]), "=r"((r)[22]), "=r"((r)[23]), \
          "=r"((r)[24]), "=r"((r)[25]), "=r"((r)[26]), "=r"((r)[27]), \
          "=r"((r)[28]), "=r"((r)[29]), "=r"((r)[30]), "=r"((r)[31]) \
        : "r"(a))
#endif

// ---------------------------- small kernels ----------------------------
__global__ void zero_denom_kernel(){
    int i = blockIdx.x*blockDim.x + threadIdx.x;
    if (i < NHEAD*S_DIM) g_dn[i] = 0.f;
}
__global__ void cvt_kernel(const float* __restrict__ src, float* __restrict__ dst, int n4){
    int i = blockIdx.x*blockDim.x + threadIdx.x;
    if (i < n4){
        float4 v = ((const float4*)src)[i];
        v.x = to_tf32(v.x); v.y = to_tf32(v.y); v.z = to_tf32(v.z); v.w = to_tf32(v.w);
        ((float4*)dst)[i] = v;
    }
}
// src [R][Cc] -> dst32 [Cc][R] (tf32); optional raw copy
template<bool DUAL>
__global__ void transpose_kernel(const float* __restrict__ src, float* __restrict__ dst32,
                                 float* __restrict__ draw, int R, int Cc){
    __shared__ float t[32][33];
    int nb = blockIdx.z;
    src   += (size_t)nb*R*Cc;
    dst32 += (size_t)nb*R*Cc;
    if (DUAL) draw += (size_t)nb*R*Cc;
    int c0 = blockIdx.x*32, r0 = blockIdx.y*32;
    int x = threadIdx.x, y = threadIdx.y;
#pragma unroll
    for (int i = 0; i < 32; i += 8)
        t[y+i][x] = src[(size_t)(r0+y+i)*Cc + c0 + x];
    __syncthreads();
#pragma unroll
    for (int i = 0; i < 32; i += 8){
        float v = t[x][y+i];
        dst32[(size_t)(c0+y+i)*R + r0 + x] = to_tf32(v);
        if (DUAL) draw[(size_t)(c0+y+i)*R + r0 + x] = v;
    }
}

// ---------------------------- tcgen05 tf32 GEMM ----------------------------
#define NSTG 3
#define SM_TMEM 0
#define SM_MB   16
#define SM_A(s) (1024u  + (uint32_t)(s)*16384u)
#define SM_B(s) (50176u + (uint32_t)(s)*16384u)
#define SMEM_BYTES 99328

struct GP {
    const float* A; const float* B; float* C;
    const float* tm; const float* im; const float* xa;
    float* dn; float* pj;
};

__device__ __forceinline__ void fill_async(const float* __restrict__ src, int ld, int rows,
                                           uint32_t base, int tid){
    int total = rows * 8;
    for (int idx = tid; idx < total; idx += 256){
        int row = idx >> 3, c4 = idx & 7;
        cp16(base + SWZ((uint32_t)row*128u + (uint32_t)c4*16u),
             src + (size_t)row*ld + c4*4);
    }
}

template<int MODE>
__global__ void __launch_bounds__(256)
tc_gemm(GP g)
{
    extern __shared__ char smem[];
    uint32_t sb = smem_u32(smem);
    const int tid = threadIdx.x, wid = tid >> 5, lid = tid & 31;
    const int m0 = blockIdx.y*128, n0 = blockIdx.x*128, bz = blockIdx.z;
    int nb, hh = 0;
    if constexpr (MODE==3 || MODE==4) { nb = bz >> 3; hh = bz & 7; } else { nb = bz; }

    constexpr int NCOL = (MODE==4) ? 96 : 128;
    constexpr int KK   = (MODE==0||MODE==1) ? T_DIM :
                         (MODE==2||MODE==5) ? C_DIM :
                         (MODE==3) ? D_DIM :
                         (MODE==4) ? L_DIM : F_DIM;
    constexpr int NT = KK / 32;
    constexpr uint32_t IDESC = (1u<<4)|(2u<<7)|(2u<<10)|((uint32_t)(NCOL/8)<<17)|(8u<<24);
    constexpr bool ROUND = (MODE==0||MODE==1||MODE==2||MODE==4||MODE==5);

    const float* Ap = nullptr; const float* Bp = nullptr; float* Cbase = nullptr;
    int ldA = 0, ldB = 0, ldC = 0;
    if constexpr (MODE==0){ Ap=g.A+(size_t)nb*L_DIM*T_DIM+(size_t)m0*T_DIM; ldA=T_DIM;
                            Bp=g.B+(size_t)n0*T_DIM; ldB=T_DIM;
                            Cbase=g.C+(size_t)nb*L_DIM*C_DIM+(size_t)m0*C_DIM+n0; ldC=C_DIM; }
    if constexpr (MODE==1){ Ap=g.A+(size_t)m0*T_DIM; ldA=T_DIM;
                            Bp=g.B+(size_t)nb*L_DIM*T_DIM+(size_t)n0*T_DIM; ldB=T_DIM;
                            Cbase=g.C+(size_t)nb*C_DIM*L_DIM+(size_t)m0*L_DIM+n0; ldC=L_DIM; }
    if constexpr (MODE==2){ Ap=g.A+(size_t)nb*S_DIM*C_DIM+(size_t)m0*C_DIM; ldA=C_DIM;
                            Bp=g.B+(size_t)n0*C_DIM; ldB=C_DIM;
                            Cbase=g.C+(size_t)nb*S_DIM*C_DIM+(size_t)m0*C_DIM+n0; ldC=C_DIM; }
    if constexpr (MODE==3){ Ap=g.A+(size_t)nb*S_DIM*C_DIM+(size_t)m0*C_DIM+hh*D_DIM; ldA=C_DIM;
                            Bp=g.B+(size_t)nb*L_DIM*C_DIM+(size_t)n0*C_DIM+hh*D_DIM; ldB=C_DIM;
                            Cbase=g.C+(size_t)bz*S_DIM*L_DIM+(size_t)m0*L_DIM+n0; ldC=L_DIM; }
    if constexpr (MODE==4){ Bp=g.B+(size_t)nb*C_DIM*L_DIM+(size_t)hh*D_DIM*L_DIM; ldB=L_DIM;
                            Cbase=g.C+(size_t)nb*S_DIM*C_DIM+(size_t)m0*C_DIM+hh*D_DIM; ldC=C_DIM; }
    if constexpr (MODE==5){ Ap=g.A+(size_t)nb*S_DIM*C_DIM+(size_t)m0*C_DIM; ldA=C_DIM;
                            Bp=g.B+(size_t)n0*C_DIM; ldB=C_DIM;
                            Cbase=g.C+(size_t)nb*S_DIM*F_DIM+(size_t)m0*F_DIM+n0; ldC=F_DIM; }
    if constexpr (MODE==6){ Ap=g.A+(size_t)m0*F_DIM; ldA=F_DIM;
                            Bp=g.B+(size_t)nb*S_DIM*F_DIM+(size_t)n0*F_DIM; ldB=F_DIM;
                            Cbase=g.C+(size_t)nb*C_DIM*S_DIM+(size_t)m0*S_DIM+n0; ldC=S_DIM; }

    float* Pj = nullptr; const float* tmn = nullptr;
    if constexpr (MODE==4){
        Pj  = g.pj + (size_t)bz*S_DIM*L_DIM + (size_t)m0*L_DIM;
        tmn = g.tm + (size_t)nb*L_DIM;
    }

#if HAS_TC
    if (wid == 0) tc_alloc(sb + SM_TMEM, 128);
    if (tid == 0){
        mbar_init(sb + SM_MB,      1);
        mbar_init(sb + SM_MB + 16, 1);
        mbar_init(sb + SM_MB + 32, 1);
    }
    __syncthreads();
    uint32_t tmem;
    asm volatile("ld.shared.b32 %0, [%1];" : "=r"(tmem) : "r"(sb + SM_TMEM));
    if (wid == 0) tc_relinquish();
#else
    float facc[NCOL];
#pragma unroll
    for (int j = 0; j < NCOL; j++) facc[j] = 0.f;
#endif

    // ---- fill one tile (tile index tt into stage s) ----
    auto fill_tile = [&](int tt, int s){
        if constexpr (MODE==4){
            const int k0 = tt*32;
            for (int idx = tid; idx < 1024; idx += 256){
                int row = idx >> 3, c4 = idx & 7;
                size_t go = (size_t)row*L_DIM + k0 + c4*4;
                float4 c = *(float4*)(Pj + go);
                float4 e;
                e.x = to_tf32(expf(c.x)); e.y = to_tf32(expf(c.y));
                e.z = to_tf32(expf(c.z)); e.w = to_tf32(expf(c.w));
                *(float4*)(smem + SM_A(s) + SWZ((uint32_t)row*128u + (uint32_t)c4*16u)) = e;
                float4 t4 = *(const float4*)(tmn + k0 + c4*4);
                c.x *= t4.x; c.y *= t4.y; c.z *= t4.z; c.w *= t4.w;
                *(float4*)(Pj + go) = c;   // final proj output: coef * tm
            }
        } else {
            fill_async(Ap + tt*32, ldA, 128, sb + SM_A(s), tid);
        }
        fill_async(Bp + tt*32, ldB, NCOL, sb + SM_B(s), tid);
    };

    int ph[NSTG] = {0,0,0};
    // prefill tiles 0 and 1
    fill_tile(0, 0); cp_commit();
    if (NT > 1){ fill_tile(1, 1); cp_commit(); }

    for (int t = 0; t < NT; t++){
        const int nf = t + 2;
        if (nf < NT){
            const int s = nf % NSTG;
#if HAS_TC
            if (nf >= NSTG){ mbar_wait(sb + SM_MB + (uint32_t)s*16u, (uint32_t)ph[s]); ph[s] ^= 1; }
#endif
            fill_tile(nf, s);
        }
        cp_commit();
        cp_wait<2>();
        __syncthreads();
        const int sc = t % NSTG;
#if HAS_TC
        if (wid == 0 && elect_one()){
            fence_proxy();
            uint64_t ad = mk_desc(sb + SM_A(sc));
            uint64_t bd = mk_desc(sb + SM_B(sc));
#pragma unroll
            for (int c = 0; c < 4; c++)
                mma_tf32(tmem, ad + c*2, bd + c*2, IDESC, (t > 0 || c > 0) ? 1u : 0u);
            tc_commit(sb + SM_MB + (uint32_t)sc*16u);
        }
#else
        if (tid < 128){
            for (int kk = 0; kk < 32; kk++){
                float a = *(const float*)(smem + SM_A(sc) + SWZ((uint32_t)tid*128u + (uint32_t)kk*4u));
#pragma unroll
                for (int j = 0; j < NCOL; j++)
                    facc[j] += a * *(const float*)(smem + SM_B(sc) + SWZ((uint32_t)j*128u + (uint32_t)kk*4u));
            }
        }
        __syncthreads();
#endif
    }
#if HAS_TC
    {
        const int sl = (NT - 1) % NSTG;
        mbar_wait(sb + SM_MB + (uint32_t)sl*16u, (uint32_t)ph[sl]);
    }
    fence_after();
#endif

    // ---------------- epilogue: warps 0-3 handle rows ----------------
    if (wid < 4){
        const int m = wid*32 + lid;
        float* Crow = Cbase + (size_t)m*ldC;
        float scl = 0.f, dv = 0.f, rsum = 0.f;
        const float* tmb = nullptr; const float* Xrow = nullptr;
        if constexpr (MODE==1) tmb = g.tm + (size_t)nb*L_DIM + n0;
        if constexpr (MODE==3){
            scl = g.im[(size_t)nb*S_DIM + m0 + m] * 0.1020620726159657f;
            tmb = g.tm + (size_t)nb*L_DIM + n0;
        }
        if constexpr (MODE==4){
            dv   = 1.f / (g.dn[(size_t)bz*S_DIM + m0 + m] + 1e-6f);
            Xrow = g.xa + (size_t)nb*S_DIM*C_DIM + (size_t)(m0 + m)*C_DIM + hh*D_DIM;
        }
        if constexpr (MODE==6)
            Xrow = g.xa + (size_t)nb*C_DIM*S_DIM + (size_t)(m0 + m)*S_DIM + n0;

#pragma unroll
        for (int ch = 0; ch < NCOL/32; ch++){
            float v[32];
#if HAS_TC
            uint32_t r[32];
            LDTM32(r, tmem + (uint32_t)ch*32u);
            tc_wait_ld();
#pragma unroll
            for (int j = 0; j < 32; j++) v[j] = __uint_as_float(r[j]);
#else
#pragma unroll
            for (int j = 0; j < 32; j++) v[j] = facc[ch*32 + j];
#endif
            if constexpr (MODE==1){
#pragma unroll
                for (int j = 0; j < 32; j++){ float tt = tmb[ch*32 + j]; v[j] *= tt*tt*tt; }
            }
            if constexpr (MODE==3){
#pragma unroll
                for (int j = 0; j < 32; j++){
                    v[j] *= scl;
                    rsum += expf(v[j]) * tmb[ch*32 + j];
                }
            }
            if constexpr (MODE==4){
#pragma unroll
                for (int j = 0; j < 32; j++) v[j] = v[j]*dv + Xrow[ch*32 + j];
            }
            if constexpr (MODE==5){
#pragma unroll
                for (int j = 0; j < 32; j++) v[j] = fmaxf(v[j], 0.f);
            }
            if constexpr (MODE==6){
#pragma unroll
                for (int j4 = 0; j4 < 8; j4++){
                    float4 xv = *(const float4*)(Xrow + ch*32 + j4*4);
                    v[j4*4+0] += xv.x; v[j4*4+1] += xv.y; v[j4*4+2] += xv.z; v[j4*4+3] += xv.w;
                }
            }
            if constexpr (ROUND){
#pragma unroll
                for (int j = 0; j < 32; j++) v[j] = to_tf32(v[j]);
            }
#pragma unroll
            for (int j4 = 0; j4 < 8; j4++)
                *(float4*)(Crow + ch*32 + j4*4) =
                    make_float4(v[j4*4], v[j4*4+1], v[j4*4+2], v[j4*4+3]);
        }
        if constexpr (MODE==3)
            atomicAdd(g.dn + (size_t)bz*S_DIM + m0 + m, rsum);
    }
#if HAS_TC
    __syncthreads();
    if (wid == 0) tc_dealloc(tmem, 128);
#endif
}

// ---------------------------- host ----------------------------
extern "C" void kernel_launch(void* const* d_in, const int* in_sizes, int n_in,
                              void* d_out, int out_size)
{
    const float* x     = (const float*)d_in[0];
    const float* xt    = (const float*)d_in[1];
    const float* tmask = (const float*)d_in[2];
    const float* im    = (const float*)d_in[3];
    const float* Wv    = (const float*)d_in[4];
    const float* Wk    = (const float*)d_in[5];
    const float* Wq    = (const float*)d_in[6];
    const float* W1    = (const float*)d_in[7];
    const float* W2    = (const float*)d_in[8];
    float* outx = (float*)d_out;
    float* proj = outx + (size_t)NBATCH*C_DIM*S_DIM;

    float *pxTr, *pxT, *pxtT, *pqt, *pkt, *pv3, *pyt, *pht, *pdn, *pw;
    cudaGetSymbolAddress((void**)&pxTr, g_xTr);
    cudaGetSymbolAddress((void**)&pxT,  g_xT);
    cudaGetSymbolAddress((void**)&pxtT, g_xtT);
    cudaGetSymbolAddress((void**)&pqt,  g_qt);
    cudaGetSymbolAddress((void**)&pkt,  g_kt);
    cudaGetSymbolAddress((void**)&pv3,  g_v3);
    cudaGetSymbolAddress((void**)&pyt,  g_yt);
    cudaGetSymbolAddress((void**)&pht,  g_ht);
    cudaGetSymbolAddress((void**)&pdn,  g_dn);
    cudaGetSymbolAddress((void**)&pw,   g_w32);

    cudaFuncSetAttribute((const void*)tc_gemm<0>, cudaFuncAttributeMaxDynamicSharedMemorySize, SMEM_BYTES);
    cudaFuncSetAttribute((const void*)tc_gemm<1>, cudaFuncAttributeMaxDynamicSharedMemorySize, SMEM_BYTES);
    cudaFuncSetAttribute((const void*)tc_gemm<2>, cudaFuncAttributeMaxDynamicSharedMemorySize, SMEM_BYTES);
    cudaFuncSetAttribute((const void*)tc_gemm<3>, cudaFuncAttributeMaxDynamicSharedMemorySize, SMEM_BYTES);
    cudaFuncSetAttribute((const void*)tc_gemm<4>, cudaFuncAttributeMaxDynamicSharedMemorySize, SMEM_BYTES);
    cudaFuncSetAttribute((const void*)tc_gemm<5>, cudaFuncAttributeMaxDynamicSharedMemorySize, SMEM_BYTES);
    cudaFuncSetAttribute((const void*)tc_gemm<6>, cudaFuncAttributeMaxDynamicSharedMemorySize, SMEM_BYTES);

    dim3 tb(32, 8);
    transpose_kernel<true ><<<dim3(S_DIM/32, C_DIM/32, NBATCH), tb>>>(x,  pxT,  pxTr, C_DIM, S_DIM);
    transpose_kernel<false><<<dim3(L_DIM/32, T_DIM/32, NBATCH), tb>>>(xt, pxtT, nullptr, T_DIM, L_DIM);
    zero_denom_kernel<<<(NHEAD*S_DIM + 255)/256, 256>>>();
    cvt_kernel<<<(C_DIM*T_DIM/4 + 255)/256, 256>>>(Wv, pw + WV_OFF, C_DIM*T_DIM/4);
    cvt_kernel<<<(C_DIM*T_DIM/4 + 255)/256, 256>>>(Wk, pw + WK_OFF, C_DIM*T_DIM/4);
    cvt_kernel<<<(C_DIM*C_DIM/4 + 255)/256, 256>>>(Wq, pw + WQ_OFF, C_DIM*C_DIM/4);
    cvt_kernel<<<(2*C_DIM*C_DIM/4 + 255)/256, 256>>>(W1, pw + W1_OFF, 2*C_DIM*C_DIM/4);
    cvt_kernel<<<(2*C_DIM*C_DIM/4 + 255)/256, 256>>>(W2, pw + W2_OFF, 2*C_DIM*C_DIM/4);

    GP g;
    // k_t[l][c] = xtT . Wk^T
    g = {pxtT, pw + WK_OFF, pkt, nullptr, nullptr, nullptr, nullptr, nullptr};
    tc_gemm<0><<<dim3(C_DIM/128, L_DIM/128, NBATCH), 256, SMEM_BYTES>>>(g);
    // v3[c][l] = (Wv . xtT^T) * tm^3
    g = {pw + WV_OFF, pxtT, pv3, tmask, nullptr, nullptr, nullptr, nullptr};
    tc_gemm<1><<<dim3(L_DIM/128, C_DIM/128, NBATCH), 256, SMEM_BYTES>>>(g);
    // q_t[s][c] = xT . Wq^T
    g = {pxT, pw + WQ_OFF, pqt, nullptr, nullptr, nullptr, nullptr, nullptr};
    tc_gemm<2><<<dim3(C_DIM/128, S_DIM/128, NBATCH), 256, SMEM_BYTES>>>(g);
    // coef[s][l] per head (+denom)
    g = {pqt, pkt, proj, tmask, im, nullptr, pdn, nullptr};
    tc_gemm<3><<<dim3(L_DIM/128, S_DIM/128, NHEAD), 256, SMEM_BYTES>>>(g);
    // xp -> y_t ; proj finalized to coef*tm
    g = {nullptr, pv3, pyt, tmask, nullptr, pxTr, pdn, proj};
    tc_gemm<4><<<dim3(1, S_DIM/128, NHEAD), 256, SMEM_BYTES>>>(g);
    // hmid = relu(y_t . W1^T)
    g = {pyt, pw + W1_OFF, pht, nullptr, nullptr, nullptr, nullptr, nullptr};
    tc_gemm<5><<<dim3(F_DIM/128, S_DIM/128, NBATCH), 256, SMEM_BYTES>>>(g);
    // out[c][s] = x + W2 . h_t^T
    g = {pw + W2_OFF, pht, outx, nullptr, nullptr, x, nullptr, nullptr};
    tc_gemm<6><<<dim3(S_DIM/128, C_DIM/128, NBATCH), 256, SMEM_BYTES>>>(g);
}

// round 5
// speedup vs baseline: 4.0313x; 1.2145x over previous
#include <cuda_runtime.h>
#include <math.h>
#include <stdint.h>

// ---- arch-feature gate: tcgen05 only exists in the sm_103a/sm_100a passes ----
#if defined(__CUDA_ARCH_FEAT_SM103_ALL) || defined(__CUDA_ARCH_FEAT_SM100_ALL) || defined(__CUDA_ARCH_FEAT_SM101_ALL)
#  define HAS_TC 1
#elif defined(__CUDA_ARCH_HAS_FEATURE__)
#  if __CUDA_ARCH_HAS_FEATURE__(SM103_ALL) || __CUDA_ARCH_HAS_FEATURE__(SM100_ALL)
#    define HAS_TC 1
#  else
#    define HAS_TC 0
#  endif
#else
#  define HAS_TC 0
#endif

#define NBATCH 2
#define C_DIM  768
#define S_DIM  4096
#define L_DIM  1024
#define D_DIM  96
#define T_DIM  384
#define F_DIM  1536
#define NHEAD  16

// ------------- scratch (__device__ globals; no allocation allowed) -------------
static __device__ float g_xTr[NBATCH*S_DIM*C_DIM];   // x^T raw   [n][s][c]
static __device__ float g_xT [NBATCH*S_DIM*C_DIM];   // x^T tf32  [n][s][c]
static __device__ float g_xtT[NBATCH*L_DIM*T_DIM];   // x_t^T tf32 [n][l][tc]
static __device__ float g_qt [NBATCH*S_DIM*C_DIM];   // q_t tf32
static __device__ float g_kt [NBATCH*L_DIM*C_DIM];   // k_t tf32
static __device__ float g_v3 [NBATCH*C_DIM*L_DIM];   // v*tm^3 tf32
static __device__ float g_yt [NBATCH*S_DIM*C_DIM];   // y^T tf32
static __device__ float g_ht [NBATCH*S_DIM*F_DIM];   // relu(W1 y) tf32
static __device__ float g_dn [NHEAD*S_DIM];          // softmax denominators
static __device__ float g_e  [(size_t)NHEAD*S_DIM*L_DIM]; // exp(coef) tf32
// tf32 copies of weights, concatenated
#define WV_OFF 0
#define WK_OFF (C_DIM*T_DIM)
#define WQ_OFF (2*C_DIM*T_DIM)
#define W1_OFF (2*C_DIM*T_DIM + C_DIM*C_DIM)
#define W2_OFF (W1_OFF + 2*C_DIM*C_DIM)
#define W_TOT  (W2_OFF + 2*C_DIM*C_DIM)
static __device__ float g_w32[W_TOT];

// ---------------------------- PTX helpers ----------------------------
__device__ __forceinline__ uint32_t smem_u32(const void* p){
    uint32_t a;
    asm("{ .reg .u64 t; cvta.to.shared.u64 t, %1; cvt.u32.u64 %0, t; }":"=r"(a):"l"(p));
    return a;
}
__device__ __forceinline__ uint32_t elect_one(){
    uint32_t r;
    asm volatile("{\n\t.reg .pred p;\n\telect.sync _|p, 0xFFFFFFFF;\n\tselp.b32 %0, 1, 0, p;\n\t}":"=r"(r));
    return r;
}
__device__ __forceinline__ float to_tf32(float x){
    uint32_t u; asm("cvt.rna.tf32.f32 %0, %1;":"=r"(u):"f"(x));
    return __uint_as_float(u);
}
#define SWZ(o) ((o) ^ ((((uint32_t)(o))>>3)&0x70u))

__device__ __forceinline__ void cp16(uint32_t dst, const void* src){
    asm volatile("cp.async.cg.shared.global [%0], [%1], 16;"::"r"(dst),"l"(src):"memory");
}
__device__ __forceinline__ void cp_commit(){
    asm volatile("cp.async.commit_group;":::"memory");
}
template<int N> __device__ __forceinline__ void cp_wait(){
    asm volatile("cp.async.wait_group %0;"::"n"(N):"memory");
}
__device__ __forceinline__ void mbar_init(uint32_t a, uint32_t cnt){
    asm volatile("mbarrier.init.shared.b64 [%0], %1;"::"r"(a),"r"(cnt):"memory");
}
__device__ __forceinline__ void mbar_wait(uint32_t a, uint32_t ph){
    asm volatile(
        "{\n\t.reg .pred P;\n\t"
        "WL%=:\n\t"
        "mbarrier.try_wait.parity.acquire.cta.shared::cta.b64 P, [%0], %1;\n\t"
        "@P bra WD%=;\n\t"
        "bra WL%=;\n\t"
        "WD%=:\n\t}"
        ::"r"(a),"r"(ph):"memory");
}
__device__ __forceinline__ void tc_commit(uint32_t mb){
#if HAS_TC
    asm volatile("tcgen05.commit.cta_group::1.mbarrier::arrive::one.shared::cluster.b64 [%0];"
                 ::"r"(mb):"memory");
#endif
}
__device__ __forceinline__ void tc_alloc(uint32_t smem_dst, uint32_t ncols){
#if HAS_TC
    asm volatile("tcgen05.alloc.cta_group::1.sync.aligned.shared::cta.b32 [%0], %1;"
                 ::"r"(smem_dst),"r"(ncols):"memory");
#endif
}
__device__ __forceinline__ void tc_dealloc(uint32_t tmem, uint32_t ncols){
#if HAS_TC
    asm volatile("tcgen05.dealloc.cta_group::1.sync.aligned.b32 %0, %1;"::"r"(tmem),"r"(ncols));
#endif
}
__device__ __forceinline__ void tc_relinquish(){
#if HAS_TC
    asm volatile("tcgen05.relinquish_alloc_permit.cta_group::1.sync.aligned;");
#endif
}
__device__ __forceinline__ void fence_after(){
#if HAS_TC
    asm volatile("tcgen05.fence::after_thread_sync;":::"memory");
#endif
}
__device__ __forceinline__ void fence_proxy(){
    asm volatile("fence.proxy.async.shared::cta;":::"memory");
}
__device__ __forceinline__ void tc_wait_ld(){
#if HAS_TC
    asm volatile("tcgen05.wait::ld.sync.aligned;":::"memory");
#endif
}
__device__ __forceinline__ uint64_t mk_desc(uint32_t addr){
    const uint64_t BASE = (uint64_t(2)<<61)|(uint64_t(1)<<46)|(uint64_t(64)<<32)|(uint64_t(1)<<16);
    return BASE | ((uint64_t)(addr>>4) & 0x3FFFull);
}
__device__ __forceinline__ void mma_tf32(uint32_t d, uint64_t ad, uint64_t bd, uint32_t idesc, uint32_t en){
#if HAS_TC
    asm volatile(
        "{\n\t.reg .pred p;\n\tsetp.ne.u32 p, %5, 0;\n\t"
        "tcgen05.mma.cta_group::1.kind::tf32 [%0], %1, %2, %3, {%4,%4,%4,%4}, p;\n\t}"
        :: "r"(d), "l"(ad), "l"(bd), "r"(idesc), "r"(0u), "r"(en) : "memory");
#endif
}
#if HAS_TC
#define LDTM32(r, a) \
    asm volatile( \
        "tcgen05.ld.sync.aligned.32x32b.x32.b32 " \
        "{%0, %1, %2, %3, %4, %5, %6, %7, " \
        " %8, %9, %10, %11, %12, %13, %14, %15, " \
        " %16, %17, %18, %19, %20, %21, %22, %23, " \
        " %24, %25, %26, %27, %28, %29, %30, %31}, [%32];" \
        : "=r"((r)[0]),  "=r"((r)[1]),  "=r"((r)[2]),  "=r"((r)[3]), \
          "=r"((r)[4]),  "=r"((r)[5]),  "=r"((r)[6]),  "=r"((r)[7]), \
          "=r"((r)[8]),  "=r"((r)[9]),  "=r"((r)[10]), "=r"((r)[11]), \
          "=r"((r)[12]), "=r"((r)[13]), "=r"((r)[14]), "=r"((r)[15]), \
          "=r"((r)[16]), "=r"((r)[17]), "=r"((r)[18]), "=r"((r)[19]), \
          "=r"((r)[20]), "=r"((r)[21]), "=r"((r)[22]), "=r"((r)[23]), \
          "=r"((r)[24]), "=r"((r)[25]), "=r"((r)[26]), "=r"((r)[27]), \
          "=r"((r)[28]), "=r"((r)[29]), "=r"((r)[30]), "=r"((r)[31]) \
        : "r"(a))
#endif

// ---------------------------- small kernels ----------------------------
// fused: tf32-convert the 5 weight matrices + zero the denominators
__global__ void prep_kernel(const float* __restrict__ Wv, const float* __restrict__ Wk,
                            const float* __restrict__ Wq, const float* __restrict__ W1,
                            const float* __restrict__ W2){
    int j = blockIdx.x*blockDim.x + threadIdx.x;
    const int NVT = C_DIM*T_DIM/4;    // 73728
    const int NQ  = C_DIM*C_DIM/4;    // 147456
    const int NF  = 2*C_DIM*C_DIM/4;  // 294912
    const float* src; float* dst;
    if (j < NVT){ src = Wv; dst = g_w32 + WV_OFF; }
    else if ((j -= NVT) < NVT){ src = Wk; dst = g_w32 + WK_OFF; }
    else if ((j -= NVT) < NQ ){ src = Wq; dst = g_w32 + WQ_OFF; }
    else if ((j -= NQ ) < NF ){ src = W1; dst = g_w32 + W1_OFF; }
    else if ((j -= NF ) < NF ){ src = W2; dst = g_w32 + W2_OFF; }
    else {
        j -= NF;
        if (j < NHEAD*S_DIM/4) ((float4*)g_dn)[j] = make_float4(0.f,0.f,0.f,0.f);
        return;
    }
    float4 v = ((const float4*)src)[j];
    v.x = to_tf32(v.x); v.y = to_tf32(v.y); v.z = to_tf32(v.z); v.w = to_tf32(v.w);
    ((float4*)dst)[j] = v;
}
#define PREP_TOTAL (2*(C_DIM*T_DIM/4) + C_DIM*C_DIM/4 + 2*(2*C_DIM*C_DIM/4) + NHEAD*S_DIM/4)

// src [R][Cc] -> dst32 [Cc][R] (tf32); optional raw copy
template<bool DUAL>
__global__ void transpose_kernel(const float* __restrict__ src, float* __restrict__ dst32,
                                 float* __restrict__ draw, int R, int Cc){
    __shared__ float t[32][33];
    int nb = blockIdx.z;
    src   += (size_t)nb*R*Cc;
    dst32 += (size_t)nb*R*Cc;
    if (DUAL) draw += (size_t)nb*R*Cc;
    int c0 = blockIdx.x*32, r0 = blockIdx.y*32;
    int x = threadIdx.x, y = threadIdx.y;
#pragma unroll
    for (int i = 0; i < 32; i += 8)
        t[y+i][x] = src[(size_t)(r0+y+i)*Cc + c0 + x];
    __syncthreads();
#pragma unroll
    for (int i = 0; i < 32; i += 8){
        float v = t[x][y+i];
        dst32[(size_t)(c0+y+i)*R + r0 + x] = to_tf32(v);
        if (DUAL) draw[(size_t)(c0+y+i)*R + r0 + x] = v;
    }
}

// ---------------------------- tcgen05 tf32 GEMM ----------------------------
#define NSTG 3
#define SM_TMEM 0
#define SM_MB   16
#define SM_A(s) (1024u  + (uint32_t)(s)*16384u)
#define SM_B(s) (50176u + (uint32_t)(s)*16384u)
#define SMEM_BYTES 99328

struct GP {
    const float* A; const float* B; float* C;
    const float* tm; const float* im; const float* xa;
    float* dn; float* e;
};

__device__ __forceinline__ void fill_async(const float* __restrict__ src, int ld, int rows,
                                           uint32_t base, int tid){
    int total = rows * 8;
    for (int idx = tid; idx < total; idx += 256){
        int row = idx >> 3, c4 = idx & 7;
        cp16(base + SWZ((uint32_t)row*128u + (uint32_t)c4*16u),
             src + (size_t)row*ld + c4*4);
    }
}

template<int MODE>
__global__ void __launch_bounds__(256)
tc_gemm(GP g)
{
    extern __shared__ char smem[];
    uint32_t sb = smem_u32(smem);
    const int tid = threadIdx.x, wid = tid >> 5, lid = tid & 31;
    const int m0 = blockIdx.y*128, n0 = blockIdx.x*128, bz = blockIdx.z;
    int nb, hh = 0;
    if constexpr (MODE==3 || MODE==4) { nb = bz >> 3; hh = bz & 7; } else { nb = bz; }

    constexpr int NCOL = (MODE==4) ? 96 : 128;
    constexpr int KK   = (MODE==0||MODE==1) ? T_DIM :
                         (MODE==2||MODE==5) ? C_DIM :
                         (MODE==3) ? D_DIM :
                         (MODE==4) ? L_DIM : F_DIM;
    constexpr int NT = KK / 32;
    constexpr uint32_t IDESC = (1u<<4)|(2u<<7)|(2u<<10)|((uint32_t)(NCOL/8)<<17)|(8u<<24);
    constexpr bool ROUND = (MODE==0||MODE==1||MODE==2||MODE==4||MODE==5);

    const float* Ap = nullptr; const float* Bp = nullptr; float* Cbase = nullptr;
    int ldA = 0, ldB = 0, ldC = 0;
    if constexpr (MODE==0){ Ap=g.A+(size_t)nb*L_DIM*T_DIM+(size_t)m0*T_DIM; ldA=T_DIM;
                            Bp=g.B+(size_t)n0*T_DIM; ldB=T_DIM;
                            Cbase=g.C+(size_t)nb*L_DIM*C_DIM+(size_t)m0*C_DIM+n0; ldC=C_DIM; }
    if constexpr (MODE==1){ Ap=g.A+(size_t)m0*T_DIM; ldA=T_DIM;
                            Bp=g.B+(size_t)nb*L_DIM*T_DIM+(size_t)n0*T_DIM; ldB=T_DIM;
                            Cbase=g.C+(size_t)nb*C_DIM*L_DIM+(size_t)m0*L_DIM+n0; ldC=L_DIM; }
    if constexpr (MODE==2){ Ap=g.A+(size_t)nb*S_DIM*C_DIM+(size_t)m0*C_DIM; ldA=C_DIM;
                            Bp=g.B+(size_t)n0*C_DIM; ldB=C_DIM;
                            Cbase=g.C+(size_t)nb*S_DIM*C_DIM+(size_t)m0*C_DIM+n0; ldC=C_DIM; }
    if constexpr (MODE==3){ Ap=g.A+(size_t)nb*S_DIM*C_DIM+(size_t)m0*C_DIM+hh*D_DIM; ldA=C_DIM;
                            Bp=g.B+(size_t)nb*L_DIM*C_DIM+(size_t)n0*C_DIM+hh*D_DIM; ldB=C_DIM;
                            Cbase=g.C+(size_t)bz*S_DIM*L_DIM+(size_t)m0*L_DIM+n0; ldC=L_DIM; }
    if constexpr (MODE==4){ Ap=g.A+(size_t)bz*S_DIM*L_DIM+(size_t)m0*L_DIM; ldA=L_DIM;
                            Bp=g.B+(size_t)nb*C_DIM*L_DIM+(size_t)hh*D_DIM*L_DIM; ldB=L_DIM;
                            Cbase=g.C+(size_t)nb*S_DIM*C_DIM+(size_t)m0*C_DIM+hh*D_DIM; ldC=C_DIM; }
    if constexpr (MODE==5){ Ap=g.A+(size_t)nb*S_DIM*C_DIM+(size_t)m0*C_DIM; ldA=C_DIM;
                            Bp=g.B+(size_t)n0*C_DIM; ldB=C_DIM;
                            Cbase=g.C+(size_t)nb*S_DIM*F_DIM+(size_t)m0*F_DIM+n0; ldC=F_DIM; }
    if constexpr (MODE==6){ Ap=g.A+(size_t)m0*F_DIM; ldA=F_DIM;
                            Bp=g.B+(size_t)nb*S_DIM*F_DIM+(size_t)n0*F_DIM; ldB=F_DIM;
                            Cbase=g.C+(size_t)nb*C_DIM*S_DIM+(size_t)m0*S_DIM+n0; ldC=S_DIM; }

#if HAS_TC
    if (wid == 0) tc_alloc(sb + SM_TMEM, 128);
    if (tid == 0){
        mbar_init(sb + SM_MB,      1);
        mbar_init(sb + SM_MB + 16, 1);
        mbar_init(sb + SM_MB + 32, 1);
    }
    __syncthreads();
    uint32_t tmem;
    asm volatile("ld.shared.b32 %0, [%1];" : "=r"(tmem) : "r"(sb + SM_TMEM));
    if (wid == 0) tc_relinquish();
#else
    float facc[NCOL];
#pragma unroll
    for (int j = 0; j < NCOL; j++) facc[j] = 0.f;
#endif

    auto fill_tile = [&](int tt, int s){
        fill_async(Ap + tt*32, ldA, 128,  sb + SM_A(s), tid);
        fill_async(Bp + tt*32, ldB, NCOL, sb + SM_B(s), tid);
    };

    int ph[NSTG] = {0,0,0};
    fill_tile(0, 0); cp_commit();
    if (NT > 1){ fill_tile(1, 1); cp_commit(); }

    for (int t = 0; t < NT; t++){
        const int nf = t + 2;
        if (nf < NT){
            const int s = nf % NSTG;
#if HAS_TC
            if (nf >= NSTG){ mbar_wait(sb + SM_MB + (uint32_t)s*16u, (uint32_t)ph[s]); ph[s] ^= 1; }
#endif
            fill_tile(nf, s);
        }
        cp_commit();
        cp_wait<2>();
        __syncthreads();
        const int sc = t % NSTG;
#if HAS_TC
        if (wid == 0 && elect_one()){
            fence_proxy();
            uint64_t ad = mk_desc(sb + SM_A(sc));
            uint64_t bd = mk_desc(sb + SM_B(sc));
#pragma unroll
            for (int c = 0; c < 4; c++)
                mma_tf32(tmem, ad + c*2, bd + c*2, IDESC, (t > 0 || c > 0) ? 1u : 0u);
            tc_commit(sb + SM_MB + (uint32_t)sc*16u);
        }
#else
        if (tid < 128){
            for (int kk = 0; kk < 32; kk++){
                float a = *(const float*)(smem + SM_A(sc) + SWZ((uint32_t)tid*128u + (uint32_t)kk*4u));
#pragma unroll
                for (int j = 0; j < NCOL; j++)
                    facc[j] += a * *(const float*)(smem + SM_B(sc) + SWZ((uint32_t)j*128u + (uint32_t)kk*4u));
            }
        }
        __syncthreads();
#endif
    }
#if HAS_TC
    {
        const int sl = (NT - 1) % NSTG;
        mbar_wait(sb + SM_MB + (uint32_t)sl*16u, (uint32_t)ph[sl]);
    }
    fence_after();
#endif

    // ---------------- epilogue: warps 0-3 handle rows ----------------
    if (wid < 4){
        const int m = wid*32 + lid;
        float* Crow = Cbase + (size_t)m*ldC;
        float scl = 0.f, dv = 0.f, rsum = 0.f;
        const float* tmb = nullptr; const float* Xrow = nullptr; float* Erow = nullptr;
        if constexpr (MODE==1) tmb = g.tm + (size_t)nb*L_DIM + n0;
        if constexpr (MODE==3){
            scl = g.im[(size_t)nb*S_DIM + m0 + m] * 0.1020620726159657f;
            tmb = g.tm + (size_t)nb*L_DIM + n0;
            Erow = g.e + (size_t)bz*S_DIM*L_DIM + (size_t)(m0 + m)*L_DIM + n0;
        }
        if constexpr (MODE==4){
            dv   = 1.f / (g.dn[(size_t)bz*S_DIM + m0 + m] + 1e-6f);
            Xrow = g.xa + (size_t)nb*S_DIM*C_DIM + (size_t)(m0 + m)*C_DIM + hh*D_DIM;
        }
        if constexpr (MODE==6)
            Xrow = g.xa + (size_t)nb*C_DIM*S_DIM + (size_t)(m0 + m)*S_DIM + n0;

#pragma unroll
        for (int ch = 0; ch < NCOL/32; ch++){
            float v[32];
#if HAS_TC
            uint32_t r[32];
            LDTM32(r, tmem + (uint32_t)ch*32u);
            tc_wait_ld();
#pragma unroll
            for (int j = 0; j < 32; j++) v[j] = __uint_as_float(r[j]);
#else
#pragma unroll
            for (int j = 0; j < 32; j++) v[j] = facc[ch*32 + j];
#endif
            if constexpr (MODE==1){
#pragma unroll
                for (int j = 0; j < 32; j++){ float tt = tmb[ch*32 + j]; v[j] *= tt*tt*tt; }
            }
            if constexpr (MODE==3){
                float ev[32];
#pragma unroll
                for (int j = 0; j < 32; j++){
                    v[j] *= scl;
                    float tt = tmb[ch*32 + j];
                    float e = expf(v[j]);
                    rsum += e * tt;
                    ev[j] = to_tf32(e);
                    v[j] *= tt;                      // final proj output: coef * tm
                }
#pragma unroll
                for (int j4 = 0; j4 < 8; j4++)
                    *(float4*)(Erow + ch*32 + j4*4) =
                        make_float4(ev[j4*4], ev[j4*4+1], ev[j4*4+2], ev[j4*4+3]);
            }
            if constexpr (MODE==4){
#pragma unroll
                for (int j = 0; j < 32; j++) v[j] = v[j]*dv + Xrow[ch*32 + j];
            }
            if constexpr (MODE==5){
#pragma unroll
                for (int j = 0; j < 32; j++) v[j] = fmaxf(v[j], 0.f);
            }
            if constexpr (MODE==6){
#pragma unroll
                for (int j4 = 0; j4 < 8; j4++){
                    float4 xv = *(const float4*)(Xrow + ch*32 + j4*4);
                    v[j4*4+0] += xv.x; v[j4*4+1] += xv.y; v[j4*4+2] += xv.z; v[j4*4+3] += xv.w;
                }
            }
            if constexpr (ROUND){
#pragma unroll
                for (int j = 0; j < 32; j++) v[j] = to_tf32(v[j]);
            }
#pragma unroll
            for (int j4 = 0; j4 < 8; j4++)
                *(float4*)(Crow + ch*32 + j4*4) =
                    make_float4(v[j4*4], v[j4*4+1], v[j4*4+2], v[j4*4+3]);
        }
        if constexpr (MODE==3)
            atomicAdd(g.dn + (size_t)bz*S_DIM + m0 + m, rsum);
    }
#if HAS_TC
    __syncthreads();
    if (wid == 0) tc_dealloc(tmem, 128);
#endif
}

// ---------------------------- host ----------------------------
extern "C" void kernel_launch(void* const* d_in, const int* in_sizes, int n_in,
                              void* d_out, int out_size)
{
    const float* x     = (const float*)d_in[0];
    const float* xt    = (const float*)d_in[1];
    const float* tmask = (const float*)d_in[2];
    const float* im    = (const float*)d_in[3];
    const float* Wv    = (const float*)d_in[4];
    const float* Wk    = (const float*)d_in[5];
    const float* Wq    = (const float*)d_in[6];
    const float* W1    = (const float*)d_in[7];
    const float* W2    = (const float*)d_in[8];
    float* outx = (float*)d_out;
    float* proj = outx + (size_t)NBATCH*C_DIM*S_DIM;

    float *pxTr, *pxT, *pxtT, *pqt, *pkt, *pv3, *pyt, *pht, *pdn, *pw, *pe;
    cudaGetSymbolAddress((void**)&pxTr, g_xTr);
    cudaGetSymbolAddress((void**)&pxT,  g_xT);
    cudaGetSymbolAddress((void**)&pxtT, g_xtT);
    cudaGetSymbolAddress((void**)&pqt,  g_qt);
    cudaGetSymbolAddress((void**)&pkt,  g_kt);
    cudaGetSymbolAddress((void**)&pv3,  g_v3);
    cudaGetSymbolAddress((void**)&pyt,  g_yt);
    cudaGetSymbolAddress((void**)&pht,  g_ht);
    cudaGetSymbolAddress((void**)&pdn,  g_dn);
    cudaGetSymbolAddress((void**)&pw,   g_w32);
    cudaGetSymbolAddress((void**)&pe,   g_e);

    cudaFuncSetAttribute((const void*)tc_gemm<0>, cudaFuncAttributeMaxDynamicSharedMemorySize, SMEM_BYTES);
    cudaFuncSetAttribute((const void*)tc_gemm<1>, cudaFuncAttributeMaxDynamicSharedMemorySize, SMEM_BYTES);
    cudaFuncSetAttribute((const void*)tc_gemm<2>, cudaFuncAttributeMaxDynamicSharedMemorySize, SMEM_BYTES);
    cudaFuncSetAttribute((const void*)tc_gemm<3>, cudaFuncAttributeMaxDynamicSharedMemorySize, SMEM_BYTES);
    cudaFuncSetAttribute((const void*)tc_gemm<4>, cudaFuncAttributeMaxDynamicSharedMemorySize, SMEM_BYTES);
    cudaFuncSetAttribute((const void*)tc_gemm<5>, cudaFuncAttributeMaxDynamicSharedMemorySize, SMEM_BYTES);
    cudaFuncSetAttribute((const void*)tc_gemm<6>, cudaFuncAttributeMaxDynamicSharedMemorySize, SMEM_BYTES);

    dim3 tb(32, 8);
    transpose_kernel<true ><<<dim3(S_DIM/32, C_DIM/32, NBATCH), tb>>>(x,  pxT,  pxTr, C_DIM, S_DIM);
    transpose_kernel<false><<<dim3(L_DIM/32, T_DIM/32, NBATCH), tb>>>(xt, pxtT, nullptr, T_DIM, L_DIM);
    prep_kernel<<<(PREP_TOTAL + 255)/256, 256>>>(Wv, Wk, Wq, W1, W2);

    GP g;
    // k_t[l][c] = xtT . Wk^T
    g = {pxtT, pw + WK_OFF, pkt, nullptr, nullptr, nullptr, nullptr, nullptr};
    tc_gemm<0><<<dim3(C_DIM/128, L_DIM/128, NBATCH), 256, SMEM_BYTES>>>(g);
    // v3[c][l] = (Wv . xtT^T) * tm^3
    g = {pw + WV_OFF, pxtT, pv3, tmask, nullptr, nullptr, nullptr, nullptr};
    tc_gemm<1><<<dim3(L_DIM/128, C_DIM/128, NBATCH), 256, SMEM_BYTES>>>(g);
    // q_t[s][c] = xT . Wq^T
    g = {pxT, pw + WQ_OFF, pqt, nullptr, nullptr, nullptr, nullptr, nullptr};
    tc_gemm<2><<<dim3(C_DIM/128, S_DIM/128, NBATCH), 256, SMEM_BYTES>>>(g);
    // coef[s][l] per head: writes final proj (=coef*tm), e scratch, denom
    g = {pqt, pkt, proj, tmask, im, nullptr, pdn, pe};
    tc_gemm<3><<<dim3(L_DIM/128, S_DIM/128, NHEAD), 256, SMEM_BYTES>>>(g);
    // xp -> y_t  (A = e scratch, pure async)
    g = {pe, pv3, pyt, tmask, nullptr, pxTr, pdn, nullptr};
    tc_gemm<4><<<dim3(1, S_DIM/128, NHEAD), 256, SMEM_BYTES>>>(g);
    // hmid = relu(y_t . W1^T)
    g = {pyt, pw + W1_OFF, pht, nullptr, nullptr, nullptr, nullptr, nullptr};
    tc_gemm<5><<<dim3(F_DIM/128, S_DIM/128, NBATCH), 256, SMEM_BYTES>>>(g);
    // out[c][s] = x + W2 . h_t^T
    g = {pw + W2_OFF, pht, outx, nullptr, nullptr, x, nullptr, nullptr};
    tc_gemm<6><<<dim3(S_DIM/128, C_DIM/128, NBATCH), 256, SMEM_BYTES>>>(g);
}

// round 6
// speedup vs baseline: 4.6600x; 1.1559x over previous
#include <cuda_runtime.h>
#include <cuda_bf16.h>
#include <math.h>
#include <stdint.h>

// ---- arch-feature gate: tcgen05 only exists in the sm_103a/sm_100a passes ----
#if defined(__CUDA_ARCH_FEAT_SM103_ALL) || defined(__CUDA_ARCH_FEAT_SM100_ALL) || defined(__CUDA_ARCH_FEAT_SM101_ALL)
#  define HAS_TC 1
#elif defined(__CUDA_ARCH_HAS_FEATURE__)
#  if __CUDA_ARCH_HAS_FEATURE__(SM103_ALL) || __CUDA_ARCH_HAS_FEATURE__(SM100_ALL)
#    define HAS_TC 1
#  else
#    define HAS_TC 0
#  endif
#else
#  define HAS_TC 0
#endif

#define NBATCH 2
#define C_DIM  768
#define S_DIM  4096
#define L_DIM  1024
#define D_DIM  96
#define T_DIM  384
#define F_DIM  1536
#define NHEAD  16

// ------------- scratch (__device__ globals; no allocation allowed) -------------
static __device__ float g_xTr[NBATCH*S_DIM*C_DIM];   // x^T raw   [n][s][c]
static __device__ float g_xT [NBATCH*S_DIM*C_DIM];   // x^T tf32  [n][s][c]
static __device__ float g_xtT[NBATCH*L_DIM*T_DIM];   // x_t^T tf32 [n][l][tc]
static __device__ float g_qt [NBATCH*S_DIM*C_DIM];   // q_t tf32
static __device__ float g_kt [NBATCH*L_DIM*C_DIM];   // k_t tf32
static __device__ float g_yt [NBATCH*S_DIM*C_DIM];   // y^T tf32
static __device__ float g_ht [NBATCH*S_DIM*F_DIM];   // relu(W1 y) tf32
static __device__ float g_dn [NHEAD*S_DIM];          // softmax denominators
static __device__ __align__(16) __nv_bfloat16 g_eb [(size_t)NHEAD*S_DIM*L_DIM]; // exp(coef) bf16
static __device__ __align__(16) __nv_bfloat16 g_v3b[NBATCH*C_DIM*L_DIM];        // v*tm^3 bf16
// tf32 copies of weights, concatenated
#define WV_OFF 0
#define WK_OFF (C_DIM*T_DIM)
#define WQ_OFF (2*C_DIM*T_DIM)
#define W1_OFF (2*C_DIM*T_DIM + C_DIM*C_DIM)
#define W2_OFF (W1_OFF + 2*C_DIM*C_DIM)
#define W_TOT  (W2_OFF + 2*C_DIM*C_DIM)
static __device__ float g_w32[W_TOT];

// ---------------------------- PTX helpers ----------------------------
__device__ __forceinline__ uint32_t smem_u32(const void* p){
    uint32_t a;
    asm("{ .reg .u64 t; cvta.to.shared.u64 t, %1; cvt.u32.u64 %0, t; }":"=r"(a):"l"(p));
    return a;
}
__device__ __forceinline__ uint32_t elect_one(){
    uint32_t r;
    asm volatile("{\n\t.reg .pred p;\n\telect.sync _|p, 0xFFFFFFFF;\n\tselp.b32 %0, 1, 0, p;\n\t}":"=r"(r));
    return r;
}
__device__ __forceinline__ float to_tf32(float x){
    uint32_t u; asm("cvt.rna.tf32.f32 %0, %1;":"=r"(u):"f"(x));
    return __uint_as_float(u);
}
__device__ __forceinline__ uint32_t pack_bf16(float lo, float hi){
    uint32_t r; asm("cvt.rn.bf16x2.f32 %0, %1, %2;":"=r"(r):"f"(hi),"f"(lo));
    return r;
}
#define SWZ(o) ((o) ^ ((((uint32_t)(o))>>3)&0x70u))

__device__ __forceinline__ void cp16(uint32_t dst, const void* src){
    asm volatile("cp.async.cg.shared.global [%0], [%1], 16;"::"r"(dst),"l"(src):"memory");
}
__device__ __forceinline__ void cp_commit(){
    asm volatile("cp.async.commit_group;":::"memory");
}
template<int N> __device__ __forceinline__ void cp_wait(){
    asm volatile("cp.async.wait_group %0;"::"n"(N):"memory");
}
__device__ __forceinline__ void mbar_init(uint32_t a, uint32_t cnt){
    asm volatile("mbarrier.init.shared.b64 [%0], %1;"::"r"(a),"r"(cnt):"memory");
}
__device__ __forceinline__ void mbar_wait(uint32_t a, uint32_t ph){
    asm volatile(
        "{\n\t.reg .pred P;\n\t"
        "WL%=:\n\t"
        "mbarrier.try_wait.parity.acquire.cta.shared::cta.b64 P, [%0], %1;\n\t"
        "@P bra WD%=;\n\t"
        "bra WL%=;\n\t"
        "WD%=:\n\t}"
        ::"r"(a),"r"(ph):"memory");
}
__device__ __forceinline__ void tc_commit(uint32_t mb){
#if HAS_TC
    asm volatile("tcgen05.commit.cta_group::1.mbarrier::arrive::one.shared::cluster.b64 [%0];"
                 ::"r"(mb):"memory");
#endif
}
__device__ __forceinline__ void tc_alloc(uint32_t smem_dst, uint32_t ncols){
#if HAS_TC
    asm volatile("tcgen05.alloc.cta_group::1.sync.aligned.shared::cta.b32 [%0], %1;"
                 ::"r"(smem_dst),"r"(ncols):"memory");
#endif
}
__device__ __forceinline__ void tc_dealloc(uint32_t tmem, uint32_t ncols){
#if HAS_TC
    asm volatile("tcgen05.dealloc.cta_group::1.sync.aligned.b32 %0, %1;"::"r"(tmem),"r"(ncols));
#endif
}
__device__ __forceinline__ void tc_relinquish(){
#if HAS_TC
    asm volatile("tcgen05.relinquish_alloc_permit.cta_group::1.sync.aligned;");
#endif
}
__device__ __forceinline__ void fence_after(){
#if HAS_TC
    asm volatile("tcgen05.fence::after_thread_sync;":::"memory");
#endif
}
__device__ __forceinline__ void fence_proxy(){
    asm volatile("fence.proxy.async.shared::cta;":::"memory");
}
__device__ __forceinline__ void tc_wait_ld(){
#if HAS_TC
    asm volatile("tcgen05.wait::ld.sync.aligned;":::"memory");
#endif
}
__device__ __forceinline__ uint64_t mk_desc(uint32_t addr){
    const uint64_t BASE = (uint64_t(2)<<61)|(uint64_t(1)<<46)|(uint64_t(64)<<32)|(uint64_t(1)<<16);
    return BASE | ((uint64_t)(addr>>4) & 0x3FFFull);
}
__device__ __forceinline__ void mma_tf32(uint32_t d, uint64_t ad, uint64_t bd, uint32_t idesc, uint32_t en){
#if HAS_TC
    asm volatile(
        "{\n\t.reg .pred p;\n\tsetp.ne.u32 p, %5, 0;\n\t"
        "tcgen05.mma.cta_group::1.kind::tf32 [%0], %1, %2, %3, {%4,%4,%4,%4}, p;\n\t}"
        :: "r"(d), "l"(ad), "l"(bd), "r"(idesc), "r"(0u), "r"(en) : "memory");
#endif
}
__device__ __forceinline__ void mma_bf16(uint32_t d, uint64_t ad, uint64_t bd, uint32_t idesc, uint32_t en){
#if HAS_TC
    asm volatile(
        "{\n\t.reg .pred p;\n\tsetp.ne.u32 p, %5, 0;\n\t"
        "tcgen05.mma.cta_group::1.kind::f16 [%0], %1, %2, %3, {%4,%4,%4,%4}, p;\n\t}"
        :: "r"(d), "l"(ad), "l"(bd), "r"(idesc), "r"(0u), "r"(en) : "memory");
#endif
}
#if HAS_TC
#define LDTM32(r, a) \
    asm volatile( \
        "tcgen05.ld.sync.aligned.32x32b.x32.b32 " \
        "{%0, %1, %2, %3, %4, %5, %6, %7, " \
        " %8, %9, %10, %11, %12, %13, %14, %15, " \
        " %16, %17, %18, %19, %20, %21, %22, %23, " \
        " %24, %25, %26, %27, %28, %29, %30, %31}, [%32];" \
        : "=r"((r)[0]),  "=r"((r)[1]),  "=r"((r)[2]),  "=r"((r)[3]), \
          "=r"((r)[4]),  "=r"((r)[5]),  "=r"((r)[6]),  "=r"((r)[7]), \
          "=r"((r)[8]),  "=r"((r)[9]),  "=r"((r)[10]), "=r"((r)[11]), \
          "=r"((r)[12]), "=r"((r)[13]), "=r"((r)[14]), "=r"((r)[15]), \
          "=r"((r)[16]), "=r"((r)[17]), "=r"((r)[18]), "=r"((r)[19]), \
          "=r"((r)[20]), "=r"((r)[21]), "=r"((r)[22]), "=r"((r)[23]), \
          "=r"((r)[24]), "=r"((r)[25]), "=r"((r)[26]), "=r"((r)[27]), \
          "=r"((r)[28]), "=r"((r)[29]), "=r"((r)[30]), "=r"((r)[31]) \
        : "r"(a))
#endif

// ---------------------------- prep (fused transposes + cvt + zero) ----------------------------
template<bool DUAL>
__device__ __forceinline__ void transpose_body(const float* __restrict__ src,
                                               float* __restrict__ dst32, float* __restrict__ draw,
                                               int R, int Cc, int bx, int by, int nb, int tid){
    __shared__ float t[32][33];
    src   += (size_t)nb*R*Cc;
    dst32 += (size_t)nb*R*Cc;
    if (DUAL) draw += (size_t)nb*R*Cc;
    int c0 = bx*32, r0 = by*32;
    int x = tid & 31, y = tid >> 5;
#pragma unroll
    for (int i = 0; i < 32; i += 8)
        t[y+i][x] = src[(size_t)(r0+y+i)*Cc + c0 + x];
    __syncthreads();
#pragma unroll
    for (int i = 0; i < 32; i += 8){
        float v = t[x][y+i];
        dst32[(size_t)(c0+y+i)*R + r0 + x] = to_tf32(v);
        if (DUAL) draw[(size_t)(c0+y+i)*R + r0 + x] = v;
    }
}

#define TRX_BLKS  (S_DIM/32 * C_DIM/32 * NBATCH)   // 6144
#define TRXT_BLKS (L_DIM/32 * T_DIM/32 * NBATCH)   // 768
#define PREP_TOTAL (2*(C_DIM*T_DIM/4) + C_DIM*C_DIM/4 + 2*(2*C_DIM*C_DIM/4) + NHEAD*S_DIM/4)
#define PREP_BLKS ((PREP_TOTAL + 255)/256)
#define PREPALL_GRID (TRX_BLKS + TRXT_BLKS + PREP_BLKS)

__global__ void __launch_bounds__(256) prep_all(
    const float* __restrict__ x, const float* __restrict__ xt,
    const float* __restrict__ Wv, const float* __restrict__ Wk, const float* __restrict__ Wq,
    const float* __restrict__ W1, const float* __restrict__ W2)
{
    int b = blockIdx.x, tid = threadIdx.x;
    if (b < TRX_BLKS){
        transpose_body<true>(x, g_xT, g_xTr, C_DIM, S_DIM, b % (S_DIM/32),
                             (b/(S_DIM/32)) % (C_DIM/32), b/(S_DIM/32 * C_DIM/32), tid);
        return;
    }
    b -= TRX_BLKS;
    if (b < TRXT_BLKS){
        transpose_body<false>(xt, g_xtT, nullptr, T_DIM, L_DIM, b % (L_DIM/32),
                              (b/(L_DIM/32)) % (T_DIM/32), b/(L_DIM/32 * T_DIM/32), tid);
        return;
    }
    b -= TRXT_BLKS;
    int j = b*256 + tid;
    const int NVT = C_DIM*T_DIM/4, NQ = C_DIM*C_DIM/4, NF = 2*C_DIM*C_DIM/4;
    const float* src; float* dst;
    if (j < NVT){ src = Wv; dst = g_w32 + WV_OFF; }
    else if ((j -= NVT) < NVT){ src = Wk; dst = g_w32 + WK_OFF; }
    else if ((j -= NVT) < NQ ){ src = Wq; dst = g_w32 + WQ_OFF; }
    else if ((j -= NQ ) < NF ){ src = W1; dst = g_w32 + W1_OFF; }
    else if ((j -= NF ) < NF ){ src = W2; dst = g_w32 + W2_OFF; }
    else {
        j -= NF;
        if (j < NHEAD*S_DIM/4) ((float4*)g_dn)[j] = make_float4(0.f,0.f,0.f,0.f);
        return;
    }
    float4 v = ((const float4*)src)[j];
    v.x = to_tf32(v.x); v.y = to_tf32(v.y); v.z = to_tf32(v.z); v.w = to_tf32(v.w);
    ((float4*)dst)[j] = v;
}

// ---------------------------- tcgen05 GEMM body ----------------------------
#define NSTG 3
#define SM_TMEM 0
#define SM_MB   16
#define SM_A(s) (1024u  + (uint32_t)(s)*16384u)
#define SM_B(s) (50176u + (uint32_t)(s)*16384u)
#define SMEM_BYTES 99328

struct GP {
    const void* A; const void* B; float* C;
    const float* tm; const float* im; const float* xa;
    float* dn; __nv_bfloat16* eb;
};

__device__ __forceinline__ void fill_async(const char* __restrict__ src, uint32_t ld_bytes,
                                           int rows, uint32_t base, int tid){
    int total = rows * 8;
    for (int idx = tid; idx < total; idx += 256){
        int row = idx >> 3, c4 = idx & 7;
        cp16(base + SWZ((uint32_t)row*128u + (uint32_t)c4*16u),
             src + (size_t)row*ld_bytes + c4*16);
    }
}

template<int MODE>
__device__ __forceinline__ void gemm_body(const GP& g, int bxx, int byy, int bz,
                                          char* smem, uint32_t sb)
{
    const int tid = threadIdx.x, wid = tid >> 5, lid = tid & 31;
    const int m0 = byy*128, n0 = bxx*128;
    int nb, hh = 0;
    if constexpr (MODE==3 || MODE==4) { nb = bz >> 3; hh = bz & 7; } else { nb = bz; }

    constexpr int NCOL = (MODE==4) ? 96 : 128;
    constexpr int KK   = (MODE==0||MODE==1) ? T_DIM :
                         (MODE==2||MODE==5) ? C_DIM :
                         (MODE==3) ? D_DIM :
                         (MODE==4) ? L_DIM : F_DIM;
    constexpr int KTILE = (MODE==4) ? 64 : 32;
    constexpr int NT = KK / KTILE;
    constexpr uint32_t AB = (MODE==4) ? 1u : 2u;   // bf16 : tf32
    constexpr uint32_t IDESC = (1u<<4)|(AB<<7)|(AB<<10)|((uint32_t)(NCOL/8)<<17)|(8u<<24);

    const char* Apb = nullptr; const char* Bpb = nullptr; float* Cbase = nullptr;
    uint32_t ldA = 0, ldB = 0; int ldC = 0;
    if constexpr (MODE==0){ Apb=(const char*)g.A + ((size_t)nb*L_DIM*T_DIM+(size_t)m0*T_DIM)*4; ldA=T_DIM*4;
                            Bpb=(const char*)g.B + (size_t)n0*T_DIM*4; ldB=T_DIM*4;
                            Cbase=g.C+(size_t)nb*L_DIM*C_DIM+(size_t)m0*C_DIM+n0; ldC=C_DIM; }
    if constexpr (MODE==1){ Apb=(const char*)g.A + (size_t)m0*T_DIM*4; ldA=T_DIM*4;
                            Bpb=(const char*)g.B + ((size_t)nb*L_DIM*T_DIM+(size_t)n0*T_DIM)*4; ldB=T_DIM*4;
                            ldC=L_DIM; }
    if constexpr (MODE==2){ Apb=(const char*)g.A + ((size_t)nb*S_DIM*C_DIM+(size_t)m0*C_DIM)*4; ldA=C_DIM*4;
                            Bpb=(const char*)g.B + (size_t)n0*C_DIM*4; ldB=C_DIM*4;
                            Cbase=g.C+(size_t)nb*S_DIM*C_DIM+(size_t)m0*C_DIM+n0; ldC=C_DIM; }
    if constexpr (MODE==3){ Apb=(const char*)g.A + ((size_t)nb*S_DIM*C_DIM+(size_t)m0*C_DIM+hh*D_DIM)*4; ldA=C_DIM*4;
                            Bpb=(const char*)g.B + ((size_t)nb*L_DIM*C_DIM+(size_t)n0*C_DIM+hh*D_DIM)*4; ldB=C_DIM*4;
                            Cbase=g.C+(size_t)bz*S_DIM*L_DIM+(size_t)m0*L_DIM+n0; ldC=L_DIM; }
    if constexpr (MODE==4){ Apb=(const char*)g.A + ((size_t)bz*S_DIM*L_DIM+(size_t)m0*L_DIM)*2; ldA=L_DIM*2;
                            Bpb=(const char*)g.B + ((size_t)nb*C_DIM*L_DIM+(size_t)hh*D_DIM*L_DIM)*2; ldB=L_DIM*2;
                            Cbase=g.C+(size_t)nb*S_DIM*C_DIM+(size_t)m0*C_DIM+hh*D_DIM; ldC=C_DIM; }
    if constexpr (MODE==5){ Apb=(const char*)g.A + ((size_t)nb*S_DIM*C_DIM+(size_t)m0*C_DIM)*4; ldA=C_DIM*4;
                            Bpb=(const char*)g.B + (size_t)n0*C_DIM*4; ldB=C_DIM*4;
                            Cbase=g.C+(size_t)nb*S_DIM*F_DIM+(size_t)m0*F_DIM+n0; ldC=F_DIM; }
    if constexpr (MODE==6){ Apb=(const char*)g.A + (size_t)m0*F_DIM*4; ldA=F_DIM*4;
                            Bpb=(const char*)g.B + ((size_t)nb*S_DIM*F_DIM+(size_t)n0*F_DIM)*4; ldB=F_DIM*4;
                            Cbase=g.C+(size_t)nb*C_DIM*S_DIM+(size_t)m0*S_DIM+n0; ldC=S_DIM; }

#if HAS_TC
    if (wid == 0) tc_alloc(sb + SM_TMEM, 128);
    if (tid == 0){
        mbar_init(sb + SM_MB,      1);
        mbar_init(sb + SM_MB + 16, 1);
        mbar_init(sb + SM_MB + 32, 1);
    }
    __syncthreads();
    uint32_t tmem;
    asm volatile("ld.shared.b32 %0, [%1];" : "=r"(tmem) : "r"(sb + SM_TMEM));
    if (wid == 0) tc_relinquish();
#else
    float facc[NCOL];
#pragma unroll
    for (int j = 0; j < NCOL; j++) facc[j] = 0.f;
#endif

    auto fill_tile = [&](int tt, int s){
        fill_async(Apb + (size_t)tt*128, ldA, 128,  sb + SM_A(s), tid);
        fill_async(Bpb + (size_t)tt*128, ldB, NCOL, sb + SM_B(s), tid);
    };

    int ph[NSTG] = {0,0,0};
    fill_tile(0, 0); cp_commit();
    if (NT > 1){ fill_tile(1, 1); cp_commit(); }

    for (int t = 0; t < NT; t++){
        const int nf = t + 2;
        if (nf < NT){
            const int s = nf % NSTG;
#if HAS_TC
            if (nf >= NSTG){ mbar_wait(sb + SM_MB + (uint32_t)s*16u, (uint32_t)ph[s]); ph[s] ^= 1; }
#endif
            fill_tile(nf, s);
        }
        cp_commit();
        cp_wait<2>();
        __syncthreads();
        const int sc = t % NSTG;
#if HAS_TC
        if (wid == 0 && elect_one()){
            fence_proxy();
            uint64_t ad = mk_desc(sb + SM_A(sc));
            uint64_t bd = mk_desc(sb + SM_B(sc));
#pragma unroll
            for (int c = 0; c < 4; c++){
                if constexpr (MODE==4)
                    mma_bf16(tmem, ad + c*2, bd + c*2, IDESC, (t > 0 || c > 0) ? 1u : 0u);
                else
                    mma_tf32(tmem, ad + c*2, bd + c*2, IDESC, (t > 0 || c > 0) ? 1u : 0u);
            }
            tc_commit(sb + SM_MB + (uint32_t)sc*16u);
        }
#else
        if (tid < 128){
            for (int kk = 0; kk < KTILE; kk++){
                float a;
                if constexpr (MODE==4)
                    a = __bfloat162float(*(const __nv_bfloat16*)(smem + SM_A(sc) + SWZ((uint32_t)tid*128u + (uint32_t)kk*2u)));
                else
                    a = *(const float*)(smem + SM_A(sc) + SWZ((uint32_t)tid*128u + (uint32_t)kk*4u));
#pragma unroll
                for (int j = 0; j < NCOL; j++){
                    float bvl;
                    if constexpr (MODE==4)
                        bvl = __bfloat162float(*(const __nv_bfloat16*)(smem + SM_B(sc) + SWZ((uint32_t)j*128u + (uint32_t)kk*2u)));
                    else
                        bvl = *(const float*)(smem + SM_B(sc) + SWZ((uint32_t)j*128u + (uint32_t)kk*4u));
                    facc[j] += a * bvl;
                }
            }
        }
        __syncthreads();
#endif
    }
#if HAS_TC
    {
        const int sl = (NT - 1) % NSTG;
        mbar_wait(sb + SM_MB + (uint32_t)sl*16u, (uint32_t)ph[sl]);
    }
    fence_after();
#endif

    // ---------------- epilogue: warps 0-3 handle rows ----------------
    if (wid < 4){
        const int m = wid*32 + lid;
        float scl = 0.f, dv = 0.f, rsum = 0.f;
        const float* tmb = nullptr; const float* Xrow = nullptr; __nv_bfloat16* Eb = nullptr;
        if constexpr (MODE==1){
            tmb = g.tm + (size_t)nb*L_DIM + n0;
            Eb  = g.eb + (size_t)nb*C_DIM*L_DIM + (size_t)(m0 + m)*L_DIM + n0;
        }
        if constexpr (MODE==3){
            scl = g.im[(size_t)nb*S_DIM + m0 + m] * 0.1020620726159657f;
            tmb = g.tm + (size_t)nb*L_DIM + n0;
            Eb  = g.eb + (size_t)bz*S_DIM*L_DIM + (size_t)(m0 + m)*L_DIM + n0;
        }
        if constexpr (MODE==4){
            dv   = 1.f / (g.dn[(size_t)bz*S_DIM + m0 + m] + 1e-6f);
            Xrow = g.xa + (size_t)nb*S_DIM*C_DIM + (size_t)(m0 + m)*C_DIM + hh*D_DIM;
        }
        if constexpr (MODE==6)
            Xrow = g.xa + (size_t)nb*C_DIM*S_DIM + (size_t)(m0 + m)*S_DIM + n0;
        float* Crow = (MODE==1) ? nullptr : Cbase + (size_t)m*ldC;

#pragma unroll
        for (int ch = 0; ch < NCOL/32; ch++){
            float v[32];
#if HAS_TC
            uint32_t r[32];
            LDTM32(r, tmem + (uint32_t)ch*32u);
            tc_wait_ld();
#pragma unroll
            for (int j = 0; j < 32; j++) v[j] = __uint_as_float(r[j]);
#else
#pragma unroll
            for (int j = 0; j < 32; j++) v[j] = facc[ch*32 + j];
#endif
            if constexpr (MODE==1){
                // v3 = acc * tm^3, stored bf16
                uint32_t pk[16];
#pragma unroll
                for (int j2 = 0; j2 < 16; j2++){
                    float t0 = tmb[ch*32 + j2*2],   a0 = v[j2*2]   * t0*t0*t0;
                    float t1 = tmb[ch*32 + j2*2+1], a1 = v[j2*2+1] * t1*t1*t1;
                    pk[j2] = pack_bf16(a0, a1);
                }
#pragma unroll
                for (int q = 0; q < 4; q++)
                    *(uint4*)(Eb + ch*32 + q*8) = make_uint4(pk[q*4],pk[q*4+1],pk[q*4+2],pk[q*4+3]);
            } else if constexpr (MODE==3){
                uint32_t pk[16];
#pragma unroll
                for (int j2 = 0; j2 < 16; j2++){
                    float c0 = v[j2*2]   * scl;
                    float c1 = v[j2*2+1] * scl;
                    float t0 = tmb[ch*32 + j2*2], t1 = tmb[ch*32 + j2*2+1];
                    float e0 = expf(c0), e1 = expf(c1);
                    rsum += e0*t0 + e1*t1;
                    pk[j2] = pack_bf16(e0, e1);
                    v[j2*2]   = c0*t0;               // final proj output: coef * tm
                    v[j2*2+1] = c1*t1;
                }
#pragma unroll
                for (int q = 0; q < 4; q++)
                    *(uint4*)(Eb + ch*32 + q*8) = make_uint4(pk[q*4],pk[q*4+1],pk[q*4+2],pk[q*4+3]);
#pragma unroll
                for (int j4 = 0; j4 < 8; j4++)
                    __stcs((float4*)(Crow + ch*32 + j4*4),
                           make_float4(v[j4*4], v[j4*4+1], v[j4*4+2], v[j4*4+3]));
            } else {
                if constexpr (MODE==4){
#pragma unroll
                    for (int j = 0; j < 32; j++) v[j] = to_tf32(v[j]*dv + Xrow[ch*32 + j]);
                }
                if constexpr (MODE==5){
#pragma unroll
                    for (int j = 0; j < 32; j++) v[j] = to_tf32(fmaxf(v[j], 0.f));
                }
                if constexpr (MODE==0 || MODE==2){
#pragma unroll
                    for (int j = 0; j < 32; j++) v[j] = to_tf32(v[j]);
                }
                if constexpr (MODE==6){
#pragma unroll
                    for (int j4 = 0; j4 < 8; j4++){
                        float4 xv = *(const float4*)(Xrow + ch*32 + j4*4);
                        v[j4*4+0] += xv.x; v[j4*4+1] += xv.y; v[j4*4+2] += xv.z; v[j4*4+3] += xv.w;
                    }
                }
#pragma unroll
                for (int j4 = 0; j4 < 8; j4++)
                    *(float4*)(Crow + ch*32 + j4*4) =
                        make_float4(v[j4*4], v[j4*4+1], v[j4*4+2], v[j4*4+3]);
            }
        }
        if constexpr (MODE==3)
            atomicAdd(g.dn + (size_t)bz*S_DIM + m0 + m, rsum);
    }
#if HAS_TC
    __syncthreads();
    if (wid == 0) tc_dealloc(tmem, 128);
#endif
}

template<int MODE>
__global__ void __launch_bounds__(256) tc_gemm(GP g){
    extern __shared__ char smem[];
    gemm_body<MODE>(g, blockIdx.x, blockIdx.y, blockIdx.z, smem, smem_u32(smem));
}

// fused launch for the 3 independent projection GEMMs (96 + 96 + 384 CTAs)
__global__ void __launch_bounds__(256) tc_gemm012(GP g0, GP g1, GP g2){
    extern __shared__ char smem[];
    uint32_t sb = smem_u32(smem);
    int b = blockIdx.x;
    if (b < 96)       gemm_body<0>(g0, b%6, (b/6)%8, b/48, smem, sb);
    else if (b < 192){ int c = b-96;  gemm_body<1>(g1, c%8, (c/8)%6, c/48,  smem, sb); }
    else             { int c = b-192; gemm_body<2>(g2, c%6, (c/6)%32, c/192, smem, sb); }
}

// ---------------------------- host ----------------------------
extern "C" void kernel_launch(void* const* d_in, const int* in_sizes, int n_in,
                              void* d_out, int out_size)
{
    const float* x     = (const float*)d_in[0];
    const float* xt    = (const float*)d_in[1];
    const float* tmask = (const float*)d_in[2];
    const float* im    = (const float*)d_in[3];
    const float* Wv    = (const float*)d_in[4];
    const float* Wk    = (const float*)d_in[5];
    const float* Wq    = (const float*)d_in[6];
    const float* W1    = (const float*)d_in[7];
    const float* W2    = (const float*)d_in[8];
    float* outx = (float*)d_out;
    float* proj = outx + (size_t)NBATCH*C_DIM*S_DIM;

    float *pxTr, *pxT, *pxtT, *pqt, *pkt, *pyt, *pht, *pdn, *pw;
    __nv_bfloat16 *peb, *pv3b;
    cudaGetSymbolAddress((void**)&pxTr, g_xTr);
    cudaGetSymbolAddress((void**)&pxT,  g_xT);
    cudaGetSymbolAddress((void**)&pxtT, g_xtT);
    cudaGetSymbolAddress((void**)&pqt,  g_qt);
    cudaGetSymbolAddress((void**)&pkt,  g_kt);
    cudaGetSymbolAddress((void**)&pyt,  g_yt);
    cudaGetSymbolAddress((void**)&pht,  g_ht);
    cudaGetSymbolAddress((void**)&pdn,  g_dn);
    cudaGetSymbolAddress((void**)&pw,   g_w32);
    cudaGetSymbolAddress((void**)&peb,  g_eb);
    cudaGetSymbolAddress((void**)&pv3b, g_v3b);

    cudaFuncSetAttribute((const void*)tc_gemm012, cudaFuncAttributeMaxDynamicSharedMemorySize, SMEM_BYTES);
    cudaFuncSetAttribute((const void*)tc_gemm<3>, cudaFuncAttributeMaxDynamicSharedMemorySize, SMEM_BYTES);
    cudaFuncSetAttribute((const void*)tc_gemm<4>, cudaFuncAttributeMaxDynamicSharedMemorySize, SMEM_BYTES);
    cudaFuncSetAttribute((const void*)tc_gemm<5>, cudaFuncAttributeMaxDynamicSharedMemorySize, SMEM_BYTES);
    cudaFuncSetAttribute((const void*)tc_gemm<6>, cudaFuncAttributeMaxDynamicSharedMemorySize, SMEM_BYTES);

    // prep: both transposes + weight cvt + denom zero, one launch
    prep_all<<<PREPALL_GRID, 256>>>(x, xt, Wv, Wk, Wq, W1, W2);

    GP g0 = {pxtT,        pw + WK_OFF, pkt, nullptr, nullptr, nullptr, nullptr, nullptr};
    GP g1 = {pw + WV_OFF, pxtT,        nullptr, tmask, nullptr, nullptr, nullptr, pv3b};
    GP g2 = {pxT,         pw + WQ_OFF, pqt, nullptr, nullptr, nullptr, nullptr, nullptr};
    tc_gemm012<<<576, 256, SMEM_BYTES>>>(g0, g1, g2);

    // coef[s][l] per head: writes final proj (=coef*tm), e bf16, denom
    GP g3 = {pqt, pkt, proj, tmask, im, nullptr, pdn, peb};
    tc_gemm<3><<<dim3(L_DIM/128, S_DIM/128, NHEAD), 256, SMEM_BYTES>>>(g3);
    // xp -> y_t (bf16 MMA: A=e, B=v3b)
    GP g4 = {peb, pv3b, pyt, nullptr, nullptr, pxTr, pdn, nullptr};
    tc_gemm<4><<<dim3(1, S_DIM/128, NHEAD), 256, SMEM_BYTES>>>(g4);
    // hmid = relu(y_t . W1^T)
    GP g5 = {pyt, pw + W1_OFF, pht, nullptr, nullptr, nullptr, nullptr, nullptr};
    tc_gemm<5><<<dim3(F_DIM/128, S_DIM/128, NBATCH), 256, SMEM_BYTES>>>(g5);
    // out[c][s] = x + W2 . h_t^T
    GP g6 = {pw + W2_OFF, pht, outx, nullptr, nullptr, x, nullptr, nullptr};
    tc_gemm<6><<<dim3(S_DIM/128, C_DIM/128, NBATCH), 256, SMEM_BYTES>>>(g6);
}

// round 7
// speedup vs baseline: 4.9893x; 1.0707x over previous
#include <cuda_runtime.h>
#include <cuda_bf16.h>
#include <math.h>
#include <stdint.h>

// ---- arch-feature gate: tcgen05 only exists in the sm_103a/sm_100a passes ----
#if defined(__CUDA_ARCH_FEAT_SM103_ALL) || defined(__CUDA_ARCH_FEAT_SM100_ALL) || defined(__CUDA_ARCH_FEAT_SM101_ALL)
#  define HAS_TC 1
#elif defined(__CUDA_ARCH_HAS_FEATURE__)
#  if __CUDA_ARCH_HAS_FEATURE__(SM103_ALL) || __CUDA_ARCH_HAS_FEATURE__(SM100_ALL)
#    define HAS_TC 1
#  else
#    define HAS_TC 0
#  endif
#else
#  define HAS_TC 0
#endif

#define NBATCH 2
#define C_DIM  768
#define S_DIM  4096
#define L_DIM  1024
#define D_DIM  96
#define T_DIM  384
#define F_DIM  1536
#define NHEAD  16

// ------------- scratch (__device__ globals; no allocation allowed) -------------
static __device__ float g_xTr[NBATCH*S_DIM*C_DIM];   // x^T raw   [n][s][c]
static __device__ float g_xT [NBATCH*S_DIM*C_DIM];   // x^T tf32  [n][s][c]
static __device__ float g_xtT[NBATCH*L_DIM*T_DIM];   // x_t^T tf32 [n][l][tc]
static __device__ float g_qt [NBATCH*S_DIM*C_DIM];   // q_t tf32
static __device__ float g_kt [NBATCH*L_DIM*C_DIM];   // k_t tf32
static __device__ float g_yt [NBATCH*S_DIM*C_DIM];   // y^T tf32
static __device__ float g_ht [NBATCH*S_DIM*F_DIM];   // relu(W1 y) tf32
static __device__ __align__(16) __nv_bfloat16 g_v3b[NBATCH*C_DIM*L_DIM]; // v*tm^3 bf16
// tf32 copies of weights, concatenated
#define WV_OFF 0
#define WK_OFF (C_DIM*T_DIM)
#define WQ_OFF (2*C_DIM*T_DIM)
#define W1_OFF (2*C_DIM*T_DIM + C_DIM*C_DIM)
#define W2_OFF (W1_OFF + 2*C_DIM*C_DIM)
#define W_TOT  (W2_OFF + 2*C_DIM*C_DIM)
static __device__ float g_w32[W_TOT];

// ---------------------------- PTX helpers ----------------------------
__device__ __forceinline__ uint32_t smem_u32(const void* p){
    uint32_t a;
    asm("{ .reg .u64 t; cvta.to.shared.u64 t, %1; cvt.u32.u64 %0, t; }":"=r"(a):"l"(p));
    return a;
}
__device__ __forceinline__ uint32_t elect_one(){
    uint32_t r;
    asm volatile("{\n\t.reg .pred p;\n\telect.sync _|p, 0xFFFFFFFF;\n\tselp.b32 %0, 1, 0, p;\n\t}":"=r"(r));
    return r;
}
__device__ __forceinline__ float to_tf32(float x){
    uint32_t u; asm("cvt.rna.tf32.f32 %0, %1;":"=r"(u):"f"(x));
    return __uint_as_float(u);
}
__device__ __forceinline__ uint32_t pack_bf16(float lo, float hi){
    uint32_t r; asm("cvt.rn.bf16x2.f32 %0, %1, %2;":"=r"(r):"f"(hi),"f"(lo));
    return r;
}
#define SWZ(o) ((o) ^ ((((uint32_t)(o))>>3)&0x70u))

__device__ __forceinline__ void cp16(uint32_t dst, const void* src){
    asm volatile("cp.async.cg.shared.global [%0], [%1], 16;"::"r"(dst),"l"(src):"memory");
}
__device__ __forceinline__ void cp_commit(){
    asm volatile("cp.async.commit_group;":::"memory");
}
template<int N> __device__ __forceinline__ void cp_wait(){
    asm volatile("cp.async.wait_group %0;"::"n"(N):"memory");
}
__device__ __forceinline__ void mbar_init(uint32_t a, uint32_t cnt){
    asm volatile("mbarrier.init.shared.b64 [%0], %1;"::"r"(a),"r"(cnt):"memory");
}
__device__ __forceinline__ void mbar_wait(uint32_t a, uint32_t ph){
    asm volatile(
        "{\n\t.reg .pred P;\n\t"
        "WL%=:\n\t"
        "mbarrier.try_wait.parity.acquire.cta.shared::cta.b64 P, [%0], %1;\n\t"
        "@P bra WD%=;\n\t"
        "bra WL%=;\n\t"
        "WD%=:\n\t}"
        ::"r"(a),"r"(ph):"memory");
}
__device__ __forceinline__ void tc_commit(uint32_t mb){
#if HAS_TC
    asm volatile("tcgen05.commit.cta_group::1.mbarrier::arrive::one.shared::cluster.b64 [%0];"
                 ::"r"(mb):"memory");
#endif
}
__device__ __forceinline__ void tc_alloc(uint32_t smem_dst, uint32_t ncols){
#if HAS_TC
    asm volatile("tcgen05.alloc.cta_group::1.sync.aligned.shared::cta.b32 [%0], %1;"
                 ::"r"(smem_dst),"r"(ncols):"memory");
#endif
}
__device__ __forceinline__ void tc_dealloc(uint32_t tmem, uint32_t ncols){
#if HAS_TC
    asm volatile("tcgen05.dealloc.cta_group::1.sync.aligned.b32 %0, %1;"::"r"(tmem),"r"(ncols));
#endif
}
__device__ __forceinline__ void tc_relinquish(){
#if HAS_TC
    asm volatile("tcgen05.relinquish_alloc_permit.cta_group::1.sync.aligned;");
#endif
}
__device__ __forceinline__ void fence_after(){
#if HAS_TC
    asm volatile("tcgen05.fence::after_thread_sync;":::"memory");
#endif
}
__device__ __forceinline__ void fence_proxy(){
    asm volatile("fence.proxy.async.shared::cta;":::"memory");
}
__device__ __forceinline__ void tc_wait_ld(){
#if HAS_TC
    asm volatile("tcgen05.wait::ld.sync.aligned;":::"memory");
#endif
}
__device__ __forceinline__ uint64_t mk_desc(uint32_t addr){
    const uint64_t BASE = (uint64_t(2)<<61)|(uint64_t(1)<<46)|(uint64_t(64)<<32)|(uint64_t(1)<<16);
    return BASE | ((uint64_t)(addr>>4) & 0x3FFFull);
}
__device__ __forceinline__ void mma_tf32(uint32_t d, uint64_t ad, uint64_t bd, uint32_t idesc, uint32_t en){
#if HAS_TC
    asm volatile(
        "{\n\t.reg .pred p;\n\tsetp.ne.u32 p, %5, 0;\n\t"
        "tcgen05.mma.cta_group::1.kind::tf32 [%0], %1, %2, %3, {%4,%4,%4,%4}, p;\n\t}"
        :: "r"(d), "l"(ad), "l"(bd), "r"(idesc), "r"(0u), "r"(en) : "memory");
#endif
}
__device__ __forceinline__ void mma_bf16(uint32_t d, uint64_t ad, uint64_t bd, uint32_t idesc, uint32_t en){
#if HAS_TC
    asm volatile(
        "{\n\t.reg .pred p;\n\tsetp.ne.u32 p, %5, 0;\n\t"
        "tcgen05.mma.cta_group::1.kind::f16 [%0], %1, %2, %3, {%4,%4,%4,%4}, p;\n\t}"
        :: "r"(d), "l"(ad), "l"(bd), "r"(idesc), "r"(0u), "r"(en) : "memory");
#endif
}
#if HAS_TC
#define LDTM32(r, a) \
    asm volatile( \
        "tcgen05.ld.sync.aligned.32x32b.x32.b32 " \
        "{%0, %1, %2, %3, %4, %5, %6, %7, " \
        " %8, %9, %10, %11, %12, %13, %14, %15, " \
        " %16, %17, %18, %19, %20, %21, %22, %23, " \
        " %24, %25, %26, %27, %28, %29, %30, %31}, [%32];" \
        : "=r"((r)[0]),  "=r"((r)[1]),  "=r"((r)[2]),  "=r"((r)[3]), \
          "=r"((r)[4]),  "=r"((r)[5]),  "=r"((r)[6]),  "=r"((r)[7]), \
          "=r"((r)[8]),  "=r"((r)[9]),  "=r"((r)[10]), "=r"((r)[11]), \
          "=r"((r)[12]), "=r"((r)[13]), "=r"((r)[14]), "=r"((r)[15]), \
          "=r"((r)[16]), "=r"((r)[17]), "=r"((r)[18]), "=r"((r)[19]), \
          "=r"((r)[20]), "=r"((r)[21]), "=r"((r)[22]), "=r"((r)[23]), \
          "=r"((r)[24]), "=r"((r)[25]), "=r"((r)[26]), "=r"((r)[27]), \
          "=r"((r)[28]), "=r"((r)[29]), "=r"((r)[30]), "=r"((r)[31]) \
        : "r"(a))
#endif

// ---------------------------- prep (fused transposes + cvt) ----------------------------
template<bool DUAL>
__device__ __forceinline__ void transpose_body(const float* __restrict__ src,
                                               float* __restrict__ dst32, float* __restrict__ draw,
                                               int R, int Cc, int bx, int by, int nb, int tid){
    __shared__ float t[32][33];
    src   += (size_t)nb*R*Cc;
    dst32 += (size_t)nb*R*Cc;
    if (DUAL) draw += (size_t)nb*R*Cc;
    int c0 = bx*32, r0 = by*32;
    int x = tid & 31, y = tid >> 5;
#pragma unroll
    for (int i = 0; i < 32; i += 8)
        t[y+i][x] = src[(size_t)(r0+y+i)*Cc + c0 + x];
    __syncthreads();
#pragma unroll
    for (int i = 0; i < 32; i += 8){
        float v = t[x][y+i];
        dst32[(size_t)(c0+y+i)*R + r0 + x] = to_tf32(v);
        if (DUAL) draw[(size_t)(c0+y+i)*R + r0 + x] = v;
    }
}

#define TRX_BLKS  (S_DIM/32 * C_DIM/32 * NBATCH)   // 6144
#define TRXT_BLKS (L_DIM/32 * T_DIM/32 * NBATCH)   // 768
#define PREP_TOTAL (2*(C_DIM*T_DIM/4) + C_DIM*C_DIM/4 + 2*(2*C_DIM*C_DIM/4))
#define PREP_BLKS ((PREP_TOTAL + 255)/256)
#define PREPALL_GRID (TRX_BLKS + TRXT_BLKS + PREP_BLKS)

__global__ void __launch_bounds__(256) prep_all(
    const float* __restrict__ x, const float* __restrict__ xt,
    const float* __restrict__ Wv, const float* __restrict__ Wk, const float* __restrict__ Wq,
    const float* __restrict__ W1, const float* __restrict__ W2)
{
    int b = blockIdx.x, tid = threadIdx.x;
    if (b < TRX_BLKS){
        transpose_body<true>(x, g_xT, g_xTr, C_DIM, S_DIM, b % (S_DIM/32),
                             (b/(S_DIM/32)) % (C_DIM/32), b/(S_DIM/32 * C_DIM/32), tid);
        return;
    }
    b -= TRX_BLKS;
    if (b < TRXT_BLKS){
        transpose_body<false>(xt, g_xtT, nullptr, T_DIM, L_DIM, b % (L_DIM/32),
                              (b/(L_DIM/32)) % (T_DIM/32), b/(L_DIM/32 * T_DIM/32), tid);
        return;
    }
    b -= TRXT_BLKS;
    int j = b*256 + tid;
    const int NVT = C_DIM*T_DIM/4, NQ = C_DIM*C_DIM/4, NF = 2*C_DIM*C_DIM/4;
    const float* src; float* dst;
    if (j < NVT){ src = Wv; dst = g_w32 + WV_OFF; }
    else if ((j -= NVT) < NVT){ src = Wk; dst = g_w32 + WK_OFF; }
    else if ((j -= NVT) < NQ ){ src = Wq; dst = g_w32 + WQ_OFF; }
    else if ((j -= NQ ) < NF ){ src = W1; dst = g_w32 + W1_OFF; }
    else if ((j -= NF ) < NF ){ src = W2; dst = g_w32 + W2_OFF; }
    else return;
    float4 v = ((const float4*)src)[j];
    v.x = to_tf32(v.x); v.y = to_tf32(v.y); v.z = to_tf32(v.z); v.w = to_tf32(v.w);
    ((float4*)dst)[j] = v;
}

// ---------------------------- generic tcgen05 GEMM (modes 0,1,2,5,6) ----------------------------
#define NSTG 3
#define SM_TMEM 0
#define SM_MB   16
#define SM_A(s) (1024u  + (uint32_t)(s)*16384u)
#define SM_B(s) (50176u + (uint32_t)(s)*16384u)
#define SMEM_BYTES 99328

struct GP {
    const void* A; const void* B; float* C;
    const float* tm; const float* xa; __nv_bfloat16* eb;
};

__device__ __forceinline__ void fill_async(const char* __restrict__ src, uint32_t ld_bytes,
                                           int rows, uint32_t base, int tid){
    int total = rows * 8;
    for (int idx = tid; idx < total; idx += 256){
        int row = idx >> 3, c4 = idx & 7;
        cp16(base + SWZ((uint32_t)row*128u + (uint32_t)c4*16u),
             src + (size_t)row*ld_bytes + c4*16);
    }
}

template<int MODE>
__device__ __forceinline__ void gemm_body(const GP& g, int bxx, int byy, int nb,
                                          char* smem, uint32_t sb)
{
    const int tid = threadIdx.x, wid = tid >> 5, lid = tid & 31;
    const int m0 = byy*128, n0 = bxx*128;
    constexpr int KK = (MODE==0||MODE==1) ? T_DIM : (MODE==2||MODE==5) ? C_DIM : F_DIM;
    constexpr int NT = KK / 32;
    constexpr uint32_t IDESC = (1u<<4)|(2u<<7)|(2u<<10)|(16u<<17)|(8u<<24);

    const char* Apb = nullptr; const char* Bpb = nullptr; float* Cbase = nullptr;
    uint32_t ldA = 0, ldB = 0; int ldC = 0;
    if constexpr (MODE==0){ Apb=(const char*)g.A + ((size_t)nb*L_DIM*T_DIM+(size_t)m0*T_DIM)*4; ldA=T_DIM*4;
                            Bpb=(const char*)g.B + (size_t)n0*T_DIM*4; ldB=T_DIM*4;
                            Cbase=g.C+(size_t)nb*L_DIM*C_DIM+(size_t)m0*C_DIM+n0; ldC=C_DIM; }
    if constexpr (MODE==1){ Apb=(const char*)g.A + (size_t)m0*T_DIM*4; ldA=T_DIM*4;
                            Bpb=(const char*)g.B + ((size_t)nb*L_DIM*T_DIM+(size_t)n0*T_DIM)*4; ldB=T_DIM*4;
                            ldC=L_DIM; }
    if constexpr (MODE==2){ Apb=(const char*)g.A + ((size_t)nb*S_DIM*C_DIM+(size_t)m0*C_DIM)*4; ldA=C_DIM*4;
                            Bpb=(const char*)g.B + (size_t)n0*C_DIM*4; ldB=C_DIM*4;
                            Cbase=g.C+(size_t)nb*S_DIM*C_DIM+(size_t)m0*C_DIM+n0; ldC=C_DIM; }
    if constexpr (MODE==5){ Apb=(const char*)g.A + ((size_t)nb*S_DIM*C_DIM+(size_t)m0*C_DIM)*4; ldA=C_DIM*4;
                            Bpb=(const char*)g.B + (size_t)n0*C_DIM*4; ldB=C_DIM*4;
                            Cbase=g.C+(size_t)nb*S_DIM*F_DIM+(size_t)m0*F_DIM+n0; ldC=F_DIM; }
    if constexpr (MODE==6){ Apb=(const char*)g.A + (size_t)m0*F_DIM*4; ldA=F_DIM*4;
                            Bpb=(const char*)g.B + ((size_t)nb*S_DIM*F_DIM+(size_t)n0*F_DIM)*4; ldB=F_DIM*4;
                            Cbase=g.C+(size_t)nb*C_DIM*S_DIM+(size_t)m0*S_DIM+n0; ldC=S_DIM; }

#if HAS_TC
    if (wid == 0) tc_alloc(sb + SM_TMEM, 128);
    if (tid == 0){
        mbar_init(sb + SM_MB,      1);
        mbar_init(sb + SM_MB + 16, 1);
        mbar_init(sb + SM_MB + 32, 1);
    }
    __syncthreads();
    uint32_t tmem;
    asm volatile("ld.shared.b32 %0, [%1];" : "=r"(tmem) : "r"(sb + SM_TMEM));
    if (wid == 0) tc_relinquish();
#else
    float facc[128];
#pragma unroll
    for (int j = 0; j < 128; j++) facc[j] = 0.f;
#endif

    auto fill_tile = [&](int tt, int s){
        fill_async(Apb + (size_t)tt*128, ldA, 128, sb + SM_A(s), tid);
        fill_async(Bpb + (size_t)tt*128, ldB, 128, sb + SM_B(s), tid);
    };

    int ph[NSTG] = {0,0,0};
    fill_tile(0, 0); cp_commit();
    if (NT > 1){ fill_tile(1, 1); cp_commit(); }

    for (int t = 0; t < NT; t++){
        const int nf = t + 2;
        if (nf < NT){
            const int s = nf % NSTG;
#if HAS_TC
            if (nf >= NSTG){ mbar_wait(sb + SM_MB + (uint32_t)s*16u, (uint32_t)ph[s]); ph[s] ^= 1; }
#endif
            fill_tile(nf, s);
        }
        cp_commit();
        cp_wait<2>();
        __syncthreads();
        const int sc = t % NSTG;
#if HAS_TC
        if (wid == 0 && elect_one()){
            fence_proxy();
            uint64_t ad = mk_desc(sb + SM_A(sc));
            uint64_t bd = mk_desc(sb + SM_B(sc));
#pragma unroll
            for (int c = 0; c < 4; c++)
                mma_tf32(tmem, ad + c*2, bd + c*2, IDESC, (t > 0 || c > 0) ? 1u : 0u);
            tc_commit(sb + SM_MB + (uint32_t)sc*16u);
        }
#else
        if (tid < 128){
            for (int kk = 0; kk < 32; kk++){
                float a = *(const float*)(smem + SM_A(sc) + SWZ((uint32_t)tid*128u + (uint32_t)kk*4u));
#pragma unroll
                for (int j = 0; j < 128; j++)
                    facc[j] += a * *(const float*)(smem + SM_B(sc) + SWZ((uint32_t)j*128u + (uint32_t)kk*4u));
            }
        }
        __syncthreads();
#endif
    }
#if HAS_TC
    {
        const int sl = (NT - 1) % NSTG;
        mbar_wait(sb + SM_MB + (uint32_t)sl*16u, (uint32_t)ph[sl]);
    }
    fence_after();
#endif

    if (wid < 4){
        const int m = wid*32 + lid;
        const float* tmb = nullptr; const float* Xrow = nullptr; __nv_bfloat16* Eb = nullptr;
        if constexpr (MODE==1){
            tmb = g.tm + (size_t)nb*L_DIM + n0;
            Eb  = g.eb + (size_t)nb*C_DIM*L_DIM + (size_t)(m0 + m)*L_DIM + n0;
        }
        if constexpr (MODE==6)
            Xrow = g.xa + (size_t)nb*C_DIM*S_DIM + (size_t)(m0 + m)*S_DIM + n0;
        float* Crow = (MODE==1) ? nullptr : Cbase + (size_t)m*ldC;

#pragma unroll
        for (int ch = 0; ch < 4; ch++){
            float v[32];
#if HAS_TC
            uint32_t r[32];
            LDTM32(r, tmem + (uint32_t)ch*32u);
            tc_wait_ld();
#pragma unroll
            for (int j = 0; j < 32; j++) v[j] = __uint_as_float(r[j]);
#else
#pragma unroll
            for (int j = 0; j < 32; j++) v[j] = facc[ch*32 + j];
#endif
            if constexpr (MODE==1){
                uint32_t pk[16];
#pragma unroll
                for (int j2 = 0; j2 < 16; j2++){
                    float t0 = tmb[ch*32 + j2*2],   a0 = v[j2*2]   * t0*t0*t0;
                    float t1 = tmb[ch*32 + j2*2+1], a1 = v[j2*2+1] * t1*t1*t1;
                    pk[j2] = pack_bf16(a0, a1);
                }
#pragma unroll
                for (int q = 0; q < 4; q++)
                    *(uint4*)(Eb + ch*32 + q*8) = make_uint4(pk[q*4],pk[q*4+1],pk[q*4+2],pk[q*4+3]);
            } else {
                if constexpr (MODE==5){
#pragma unroll
                    for (int j = 0; j < 32; j++) v[j] = to_tf32(fmaxf(v[j], 0.f));
                }
                if constexpr (MODE==0 || MODE==2){
#pragma unroll
                    for (int j = 0; j < 32; j++) v[j] = to_tf32(v[j]);
                }
                if constexpr (MODE==6){
#pragma unroll
                    for (int j4 = 0; j4 < 8; j4++){
                        float4 xv = *(const float4*)(Xrow + ch*32 + j4*4);
                        v[j4*4+0] += xv.x; v[j4*4+1] += xv.y; v[j4*4+2] += xv.z; v[j4*4+3] += xv.w;
                    }
                }
#pragma unroll
                for (int j4 = 0; j4 < 8; j4++)
                    *(float4*)(Crow + ch*32 + j4*4) =
                        make_float4(v[j4*4], v[j4*4+1], v[j4*4+2], v[j4*4+3]);
            }
        }
    }
#if HAS_TC
    __syncthreads();
    if (wid == 0) tc_dealloc(tmem, 128);
#endif
}

template<int MODE>
__global__ void __launch_bounds__(256) tc_gemm(GP g){
    extern __shared__ char smem[];
    gemm_body<MODE>(g, blockIdx.x, blockIdx.y, blockIdx.z, smem, smem_u32(smem));
}

// fused launch for the 3 independent projection GEMMs (96 + 96 + 384 CTAs)
__global__ void __launch_bounds__(256) tc_gemm012(GP g0, GP g1, GP g2){
    extern __shared__ char smem[];
    uint32_t sb = smem_u32(smem);
    int b = blockIdx.x;
    if (b < 96)       gemm_body<0>(g0, b%6, (b/6)%8, b/48, smem, sb);
    else if (b < 192){ int c = b-96;  gemm_body<1>(g1, c%8, (c/8)%6, c/48,  smem, sb); }
    else             { int c = b-192; gemm_body<2>(g2, c%6, (c/6)%32, c/192, smem, sb); }
}

// ---------------------------- fused attention kernel ----------------------------
// per CTA: one 128-row s-block of one (n,h).  q tile resident; loop 8 l-blocks:
// qk tf32 MMA -> convert (proj write, e bf16 to SMEM, denom accum) -> e@v3 bf16 MMA.
#define AT_MB    16u
#define AT_QT    1024u                         // 3 x 16384
#define AT_E     (AT_QT + 49152u)              // 32768 (2 sub-tiles of 16384)
#define AT_KT(s) (AT_E + 32768u + (uint32_t)(s)*49152u)
#define AT_V3(s) (AT_E + 32768u + 98304u + (uint32_t)(s)*24576u)
#define AT_SMEM  230400u

__global__ void __launch_bounds__(256) attn_kernel(
    const float* __restrict__ qt, const float* __restrict__ kt,
    const __nv_bfloat16* __restrict__ v3b,
    const float* __restrict__ im, const float* __restrict__ tm,
    const float* __restrict__ xTr, float* __restrict__ proj, float* __restrict__ yt)
{
    extern __shared__ char smem[];
    uint32_t sb = smem_u32(smem);
    const int tid = threadIdx.x, wid = tid >> 5, lid = tid & 31;
    const int bz = blockIdx.z, nb = bz >> 3, hh = bz & 7;
    const int m0 = blockIdx.y * 128;

    const char* Aq = (const char*)(qt  + (size_t)nb*S_DIM*C_DIM + (size_t)m0*C_DIM + hh*D_DIM);
    const char* Bk = (const char*)(kt  + (size_t)nb*L_DIM*C_DIM + hh*D_DIM);
    const char* Vb = (const char*)(v3b + (size_t)nb*C_DIM*L_DIM + (size_t)hh*D_DIM*L_DIM);
    float* Pj = proj + (size_t)bz*S_DIM*L_DIM + (size_t)m0*L_DIM;

    constexpr uint32_t ID_QK = (1u<<4)|(2u<<7)|(2u<<10)|(16u<<17)|(8u<<24);  // tf32, N=128
    constexpr uint32_t ID_PV = (1u<<4)|(1u<<7)|(1u<<10)|(12u<<17)|(8u<<24);  // bf16, N=96

#if HAS_TC
    if (wid == 0) tc_alloc(sb, 512);
    if (tid == 0){
        mbar_init(sb + AT_MB,      1);   // qk buf0
        mbar_init(sb + AT_MB + 16, 1);   // qk buf1
        mbar_init(sb + AT_MB + 32, 1);   // pv
    }
    __syncthreads();
    uint32_t tmem;
    asm volatile("ld.shared.b32 %0, [%1];" : "=r"(tmem) : "r"(sb));
    if (wid == 0) tc_relinquish();

    auto fill_kv = [&](int blk, int s){
        const char* Bkb = Bk + (size_t)blk*128*C_DIM*4;
#pragma unroll
        for (int t = 0; t < 3; t++)
            fill_async(Bkb + t*128, C_DIM*4, 128, sb + AT_KT(s) + (uint32_t)t*16384u, tid);
#pragma unroll
        for (int t2 = 0; t2 < 2; t2++)
            fill_async(Vb + (size_t)blk*256 + t2*128, L_DIM*2, 96,
                       sb + AT_V3(s) + (uint32_t)t2*12288u, tid);
    };
    auto issue_qk = [&](int blk, int buf){
        if (wid == 0 && elect_one()){
            fence_proxy();
#pragma unroll
            for (int t = 0; t < 3; t++){
                uint64_t ad = mk_desc(sb + AT_QT + (uint32_t)t*16384u);
                uint64_t bd = mk_desc(sb + AT_KT(blk&1) + (uint32_t)t*16384u);
#pragma unroll
                for (int c = 0; c < 4; c++)
                    mma_tf32(tmem + (uint32_t)buf*128u, ad + c*2, bd + c*2, ID_QK,
                             (t > 0 || c > 0) ? 1u : 0u);
            }
            tc_commit(sb + AT_MB + (uint32_t)buf*16u);
        }
    };
    auto issue_pv = [&](int blk){
        if (wid == 0 && elect_one()){
            fence_proxy();
#pragma unroll
            for (int t2 = 0; t2 < 2; t2++){
                uint64_t ad = mk_desc(sb + AT_E + (uint32_t)t2*16384u);
                uint64_t bd = mk_desc(sb + AT_V3(blk&1) + (uint32_t)t2*12288u);
#pragma unroll
                for (int c = 0; c < 4; c++)
                    mma_bf16(tmem + 256u, ad + c*2, bd + c*2, ID_PV,
                             (blk > 0 || t2 > 0 || c > 0) ? 1u : 0u);
            }
            tc_commit(sb + AT_MB + 32u);
        }
    };

    // prologue: q tile + first kv stage
#pragma unroll
    for (int t = 0; t < 3; t++)
        fill_async(Aq + t*128, C_DIM*4, 128, sb + AT_QT + (uint32_t)t*16384u, tid);
    cp_commit();
    fill_kv(0, 0);
    cp_commit();
    cp_wait<0>();
    __syncthreads();
    issue_qk(0, 0);

    // per-thread convert constants: all 8 warps convert (0-3: cols 0-63, 4-7: 64-127)
    const int mrow = (wid & 3)*32 + lid;
    const int cbase = (wid >> 2)*64;
    const float scl = im[(size_t)nb*S_DIM + m0 + mrow] * 0.1020620726159657f;
    float rsum = 0.f;

    int phq[2] = {0,0}, php = 0;
    for (int blk = 0; blk < 8; blk++){
        if (blk > 0){ mbar_wait(sb + AT_MB + 32u, (uint32_t)php); php ^= 1; }
        if (blk + 1 < 8){ fill_kv(blk + 1, (blk + 1)&1); }
        cp_commit();

        mbar_wait(sb + AT_MB + (uint32_t)(blk&1)*16u, (uint32_t)phq[blk&1]); phq[blk&1] ^= 1;
        fence_after();

        // convert coef tile D1(blk&1): proj out, e bf16 to SMEM, denom accumulate
        {
            const float* tmb = tm + (size_t)nb*L_DIM + blk*128 + cbase;
            float* prow = Pj + (size_t)mrow*L_DIM + blk*128 + cbase;
#pragma unroll
            for (int ch = 0; ch < 2; ch++){
                uint32_t r[32];
                LDTM32(r, tmem + (uint32_t)(blk&1)*128u + (uint32_t)cbase + (uint32_t)ch*32u);
                tc_wait_ld();
                uint32_t pk[16]; float vv[32];
#pragma unroll
                for (int j2 = 0; j2 < 16; j2++){
                    float c0 = __uint_as_float(r[j2*2])   * scl;
                    float c1 = __uint_as_float(r[j2*2+1]) * scl;
                    float t0 = tmb[ch*32 + j2*2], t1 = tmb[ch*32 + j2*2+1];
                    float e0 = expf(c0), e1 = expf(c1);
                    rsum += e0*t0 + e1*t1;
                    pk[j2] = pack_bf16(e0, e1);
                    vv[j2*2]   = c0*t0;
                    vv[j2*2+1] = c1*t1;
                }
                const int col = cbase + ch*32;
                const uint32_t t2 = (uint32_t)(col >> 6);
                const uint32_t off = (uint32_t)((col & 63) * 2);
                uint32_t eb = sb + AT_E + t2*16384u + 0u;
#pragma unroll
                for (int q = 0; q < 4; q++)
                    *(uint4*)(smem + (eb - sb) + SWZ((uint32_t)mrow*128u + off + (uint32_t)q*16u))
                        = make_uint4(pk[q*4],pk[q*4+1],pk[q*4+2],pk[q*4+3]);
#pragma unroll
                for (int q = 0; q < 8; q++)
                    __stcs((float4*)(prow + ch*32 + q*4),
                           make_float4(vv[q*4], vv[q*4+1], vv[q*4+2], vv[q*4+3]));
            }
        }
        __syncthreads();
        issue_pv(blk);
        if (blk + 1 < 8){
            cp_wait<0>();
            __syncthreads();
            issue_qk(blk + 1, (blk + 1)&1);
        }
    }
    mbar_wait(sb + AT_MB + 32u, (uint32_t)php);
    fence_after();

    // combine denominator halves
    float* rs = (float*)(smem + AT_E);
    rs[(wid>>2)*128 + mrow] = rsum;
    __syncthreads();

    // epilogue: xp from TMEM, scale, add x, write y_t
    if (wid < 4){
        const int m = wid*32 + lid;
        const float dv = 1.f / (rs[m] + rs[128 + m] + 1e-6f);
        const float* Xrow = xTr + (size_t)nb*S_DIM*C_DIM + (size_t)(m0 + m)*C_DIM + hh*D_DIM;
        float* Yrow = yt + (size_t)nb*S_DIM*C_DIM + (size_t)(m0 + m)*C_DIM + hh*D_DIM;
#pragma unroll
        for (int ch = 0; ch < 3; ch++){
            uint32_t r[32];
            LDTM32(r, tmem + 256u + (uint32_t)ch*32u);
            tc_wait_ld();
            float v[32];
#pragma unroll
            for (int j = 0; j < 32; j++)
                v[j] = to_tf32(__uint_as_float(r[j])*dv + Xrow[ch*32 + j]);
#pragma unroll
            for (int q = 0; q < 8; q++)
                *(float4*)(Yrow + ch*32 + q*4) = make_float4(v[q*4],v[q*4+1],v[q*4+2],v[q*4+3]);
        }
    }
    __syncthreads();
    if (wid == 0) tc_dealloc(tmem, 512);
#else
    // fallback (never executed on sm_103a hardware): naive but correct
    for (int m = tid; m < 128; m += 256){
        float scl = im[(size_t)nb*S_DIM + m0 + m] * 0.1020620726159657f;
        const float* qrow = qt + (size_t)nb*S_DIM*C_DIM + (size_t)(m0+m)*C_DIM + hh*D_DIM;
        float xp[96];
#pragma unroll
        for (int d = 0; d < 96; d++) xp[d] = 0.f;
        float rsum = 0.f;
        for (int l = 0; l < L_DIM; l++){
            const float* krow = kt + (size_t)nb*L_DIM*C_DIM + (size_t)l*C_DIM + hh*D_DIM;
            float c = 0.f;
            for (int d = 0; d < 96; d++) c += qrow[d]*krow[d];
            c *= scl;
            float t = tm[(size_t)nb*L_DIM + l];
            Pj[(size_t)m*L_DIM + l] = c*t;
            float e = expf(c);
            rsum += e*t;
            float eb = __bfloat162float(__float2bfloat16(e));
            for (int d = 0; d < 96; d++)
                xp[d] += eb * __bfloat162float(v3b[(size_t)nb*C_DIM*L_DIM + (size_t)(hh*D_DIM+d)*L_DIM + l]);
        }
        float dv = 1.f/(rsum + 1e-6f);
        for (int d = 0; d < 96; d++)
            yt[(size_t)nb*S_DIM*C_DIM + (size_t)(m0+m)*C_DIM + hh*D_DIM + d] =
                to_tf32(xp[d]*dv + xTr[(size_t)nb*S_DIM*C_DIM + (size_t)(m0+m)*C_DIM + hh*D_DIM + d]);
    }
#endif
}

// ---------------------------- host ----------------------------
extern "C" void kernel_launch(void* const* d_in, const int* in_sizes, int n_in,
                              void* d_out, int out_size)
{
    const float* x     = (const float*)d_in[0];
    const float* xt    = (const float*)d_in[1];
    const float* tmask = (const float*)d_in[2];
    const float* im    = (const float*)d_in[3];
    const float* Wv    = (const float*)d_in[4];
    const float* Wk    = (const float*)d_in[5];
    const float* Wq    = (const float*)d_in[6];
    const float* W1    = (const float*)d_in[7];
    const float* W2    = (const float*)d_in[8];
    float* outx = (float*)d_out;
    float* proj = outx + (size_t)NBATCH*C_DIM*S_DIM;

    float *pxTr, *pxT, *pxtT, *pqt, *pkt, *pyt, *pht, *pw;
    __nv_bfloat16 *pv3b;
    cudaGetSymbolAddress((void**)&pxTr, g_xTr);
    cudaGetSymbolAddress((void**)&pxT,  g_xT);
    cudaGetSymbolAddress((void**)&pxtT, g_xtT);
    cudaGetSymbolAddress((void**)&pqt,  g_qt);
    cudaGetSymbolAddress((void**)&pkt,  g_kt);
    cudaGetSymbolAddress((void**)&pyt,  g_yt);
    cudaGetSymbolAddress((void**)&pht,  g_ht);
    cudaGetSymbolAddress((void**)&pw,   g_w32);
    cudaGetSymbolAddress((void**)&pv3b, g_v3b);

    cudaFuncSetAttribute((const void*)tc_gemm012, cudaFuncAttributeMaxDynamicSharedMemorySize, SMEM_BYTES);
    cudaFuncSetAttribute((const void*)attn_kernel, cudaFuncAttributeMaxDynamicSharedMemorySize, AT_SMEM);
    cudaFuncSetAttribute((const void*)tc_gemm<5>, cudaFuncAttributeMaxDynamicSharedMemorySize, SMEM_BYTES);
    cudaFuncSetAttribute((const void*)tc_gemm<6>, cudaFuncAttributeMaxDynamicSharedMemorySize, SMEM_BYTES);

    // prep: both transposes + weight cvt, one launch
    prep_all<<<PREPALL_GRID, 256>>>(x, xt, Wv, Wk, Wq, W1, W2);

    GP g0 = {pxtT,        pw + WK_OFF, pkt,     nullptr, nullptr, nullptr};
    GP g1 = {pw + WV_OFF, pxtT,        nullptr, tmask,   nullptr, pv3b};
    GP g2 = {pxT,         pw + WQ_OFF, pqt,     nullptr, nullptr, nullptr};
    tc_gemm012<<<576, 256, SMEM_BYTES>>>(g0, g1, g2);

    // fused attention: proj (final), y_t
    attn_kernel<<<dim3(1, S_DIM/128, NHEAD), 256, AT_SMEM>>>(
        pqt, pkt, pv3b, im, tmask, pxTr, proj, pyt);

    // hmid = relu(y_t . W1^T)
    GP g5 = {pyt, pw + W1_OFF, pht, nullptr, nullptr, nullptr};
    tc_gemm<5><<<dim3(F_DIM/128, S_DIM/128, NBATCH), 256, SMEM_BYTES>>>(g5);
    // out[c][s] = x + W2 . h_t^T
    GP g6 = {pw + W2_OFF, pht, outx, nullptr, x, nullptr};
    tc_gemm<6><<<dim3(S_DIM/128, C_DIM/128, NBATCH), 256, SMEM_BYTES>>>(g6);
}

// round 8
// speedup vs baseline: 5.4715x; 1.0966x over previous
#include <cuda_runtime.h>
#include <cuda_bf16.h>
#include <math.h>
#include <stdint.h>

// ---- arch-feature gate: tcgen05 only exists in the sm_103a/sm_100a passes ----
#if defined(__CUDA_ARCH_FEAT_SM103_ALL) || defined(__CUDA_ARCH_FEAT_SM100_ALL) || defined(__CUDA_ARCH_FEAT_SM101_ALL)
#  define HAS_TC 1
#elif defined(__CUDA_ARCH_HAS_FEATURE__)
#  if __CUDA_ARCH_HAS_FEATURE__(SM103_ALL) || __CUDA_ARCH_HAS_FEATURE__(SM100_ALL)
#    define HAS_TC 1
#  else
#    define HAS_TC 0
#  endif
#else
#  define HAS_TC 0
#endif

#define NBATCH 2
#define C_DIM  768
#define S_DIM  4096
#define L_DIM  1024
#define D_DIM  96
#define T_DIM  384
#define F_DIM  1536
#define NHEAD  16

// ------------- scratch (__device__ globals; no allocation allowed) -------------
static __device__ float g_xTr[NBATCH*S_DIM*C_DIM];   // x^T raw   [n][s][c]
static __device__ float g_xT [NBATCH*S_DIM*C_DIM];   // x^T tf32  [n][s][c]
static __device__ float g_xtT[NBATCH*L_DIM*T_DIM];   // x_t^T tf32 [n][l][tc]
static __device__ float g_qt [NBATCH*S_DIM*C_DIM];   // q_t tf32
static __device__ float g_kt [NBATCH*L_DIM*C_DIM];   // k_t tf32
static __device__ float g_yt [NBATCH*S_DIM*C_DIM];   // y^T tf32
static __device__ float g_ht [NBATCH*S_DIM*F_DIM];   // relu(W1 y) tf32
static __device__ __align__(16) __nv_bfloat16 g_v3b[NBATCH*C_DIM*L_DIM]; // v*tm^3 bf16
// tf32 copies of weights, concatenated
#define WV_OFF 0
#define WK_OFF (C_DIM*T_DIM)
#define WQ_OFF (2*C_DIM*T_DIM)
#define W1_OFF (2*C_DIM*T_DIM + C_DIM*C_DIM)
#define W2_OFF (W1_OFF + 2*C_DIM*C_DIM)
#define W_TOT  (W2_OFF + 2*C_DIM*C_DIM)
static __device__ float g_w32[W_TOT];

// ---------------------------- PTX helpers ----------------------------
__device__ __forceinline__ uint32_t smem_u32(const void* p){
    uint32_t a;
    asm("{ .reg .u64 t; cvta.to.shared.u64 t, %1; cvt.u32.u64 %0, t; }":"=r"(a):"l"(p));
    return a;
}
__device__ __forceinline__ uint32_t elect_one(){
    uint32_t r;
    asm volatile("{\n\t.reg .pred p;\n\telect.sync _|p, 0xFFFFFFFF;\n\tselp.b32 %0, 1, 0, p;\n\t}":"=r"(r));
    return r;
}
__device__ __forceinline__ float to_tf32(float x){
    uint32_t u; asm("cvt.rna.tf32.f32 %0, %1;":"=r"(u):"f"(x));
    return __uint_as_float(u);
}
__device__ __forceinline__ uint32_t pack_bf16(float lo, float hi){
    uint32_t r; asm("cvt.rn.bf16x2.f32 %0, %1, %2;":"=r"(r):"f"(hi),"f"(lo));
    return r;
}
#define SWZ(o) ((o) ^ ((((uint32_t)(o))>>3)&0x70u))

__device__ __forceinline__ void cp16(uint32_t dst, const void* src){
    asm volatile("cp.async.cg.shared.global [%0], [%1], 16;"::"r"(dst),"l"(src):"memory");
}
__device__ __forceinline__ void cp_commit(){
    asm volatile("cp.async.commit_group;":::"memory");
}
template<int N> __device__ __forceinline__ void cp_wait(){
    asm volatile("cp.async.wait_group %0;"::"n"(N):"memory");
}
__device__ __forceinline__ void mbar_init(uint32_t a, uint32_t cnt){
    asm volatile("mbarrier.init.shared.b64 [%0], %1;"::"r"(a),"r"(cnt):"memory");
}
__device__ __forceinline__ void mbar_wait(uint32_t a, uint32_t ph){
    asm volatile(
        "{\n\t.reg .pred P;\n\t"
        "WL%=:\n\t"
        "mbarrier.try_wait.parity.acquire.cta.shared::cta.b64 P, [%0], %1;\n\t"
        "@P bra WD%=;\n\t"
        "bra WL%=;\n\t"
        "WD%=:\n\t}"
        ::"r"(a),"r"(ph):"memory");
}
__device__ __forceinline__ void tc_commit(uint32_t mb){
#if HAS_TC
    asm volatile("tcgen05.commit.cta_group::1.mbarrier::arrive::one.shared::cluster.b64 [%0];"
                 ::"r"(mb):"memory");
#endif
}
__device__ __forceinline__ void tc_alloc(uint32_t smem_dst, uint32_t ncols){
#if HAS_TC
    asm volatile("tcgen05.alloc.cta_group::1.sync.aligned.shared::cta.b32 [%0], %1;"
                 ::"r"(smem_dst),"r"(ncols):"memory");
#endif
}
__device__ __forceinline__ void tc_dealloc(uint32_t tmem, uint32_t ncols){
#if HAS_TC
    asm volatile("tcgen05.dealloc.cta_group::1.sync.aligned.b32 %0, %1;"::"r"(tmem),"r"(ncols));
#endif
}
__device__ __forceinline__ void tc_relinquish(){
#if HAS_TC
    asm volatile("tcgen05.relinquish_alloc_permit.cta_group::1.sync.aligned;");
#endif
}
__device__ __forceinline__ void fence_after(){
#if HAS_TC
    asm volatile("tcgen05.fence::after_thread_sync;":::"memory");
#endif
}
__device__ __forceinline__ void fence_proxy(){
    asm volatile("fence.proxy.async.shared::cta;":::"memory");
}
__device__ __forceinline__ void tc_wait_ld(){
#if HAS_TC
    asm volatile("tcgen05.wait::ld.sync.aligned;":::"memory");
#endif
}
__device__ __forceinline__ uint64_t mk_desc(uint32_t addr){
    const uint64_t BASE = (uint64_t(2)<<61)|(uint64_t(1)<<46)|(uint64_t(64)<<32)|(uint64_t(1)<<16);
    return BASE | ((uint64_t)(addr>>4) & 0x3FFFull);
}
__device__ __forceinline__ void mma_tf32(uint32_t d, uint64_t ad, uint64_t bd, uint32_t idesc, uint32_t en){
#if HAS_TC
    asm volatile(
        "{\n\t.reg .pred p;\n\tsetp.ne.u32 p, %5, 0;\n\t"
        "tcgen05.mma.cta_group::1.kind::tf32 [%0], %1, %2, %3, {%4,%4,%4,%4}, p;\n\t}"
        :: "r"(d), "l"(ad), "l"(bd), "r"(idesc), "r"(0u), "r"(en) : "memory");
#endif
}
__device__ __forceinline__ void mma_bf16(uint32_t d, uint64_t ad, uint64_t bd, uint32_t idesc, uint32_t en){
#if HAS_TC
    asm volatile(
        "{\n\t.reg .pred p;\n\tsetp.ne.u32 p, %5, 0;\n\t"
        "tcgen05.mma.cta_group::1.kind::f16 [%0], %1, %2, %3, {%4,%4,%4,%4}, p;\n\t}"
        :: "r"(d), "l"(ad), "l"(bd), "r"(idesc), "r"(0u), "r"(en) : "memory");
#endif
}
#if HAS_TC
#define LDTM32(r, a) \
    asm volatile( \
        "tcgen05.ld.sync.aligned.32x32b.x32.b32 " \
        "{%0, %1, %2, %3, %4, %5, %6, %7, " \
        " %8, %9, %10, %11, %12, %13, %14, %15, " \
        " %16, %17, %18, %19, %20, %21, %22, %23, " \
        " %24, %25, %26, %27, %28, %29, %30, %31}, [%32];" \
        : "=r"((r)[0]),  "=r"((r)[1]),  "=r"((r)[2]),  "=r"((r)[3]), \
          "=r"((r)[4]),  "=r"((r)[5]),  "=r"((r)[6]),  "=r"((r)[7]), \
          "=r"((r)[8]),  "=r"((r)[9]),  "=r"((r)[10]), "=r"((r)[11]), \
          "=r"((r)[12]), "=r"((r)[13]), "=r"((r)[14]), "=r"((r)[15]), \
          "=r"((r)[16]), "=r"((r)[17]), "=r"((r)[18]), "=r"((r)[19]), \
          "=r"((r)[20]), "=r"((r)[21]), "=r"((r)[22]), "=r"((r)[23]), \
          "=r"((r)[24]), "=r"((r)[25]), "=r"((r)[26]), "=r"((r)[27]), \
          "=r"((r)[28]), "=r"((r)[29]), "=r"((r)[30]), "=r"((r)[31]) \
        : "r"(a))
#endif

// ---------------------------- prep (fused transposes + cvt) ----------------------------
template<bool DUAL>
__device__ __forceinline__ void transpose_body(const float* __restrict__ src,
                                               float* __restrict__ dst32, float* __restrict__ draw,
                                               int R, int Cc, int bx, int by, int nb, int tid){
    __shared__ float t[32][33];
    src   += (size_t)nb*R*Cc;
    dst32 += (size_t)nb*R*Cc;
    if (DUAL) draw += (size_t)nb*R*Cc;
    int c0 = bx*32, r0 = by*32;
    int x = tid & 31, y = tid >> 5;
#pragma unroll
    for (int i = 0; i < 32; i += 8)
        t[y+i][x] = src[(size_t)(r0+y+i)*Cc + c0 + x];
    __syncthreads();
#pragma unroll
    for (int i = 0; i < 32; i += 8){
        float v = t[x][y+i];
        dst32[(size_t)(c0+y+i)*R + r0 + x] = to_tf32(v);
        if (DUAL) draw[(size_t)(c0+y+i)*R + r0 + x] = v;
    }
}

#define TRX_BLKS  (S_DIM/32 * C_DIM/32 * NBATCH)   // 6144
#define TRXT_BLKS (L_DIM/32 * T_DIM/32 * NBATCH)   // 768
#define PREP_TOTAL (2*(C_DIM*T_DIM/4) + C_DIM*C_DIM/4 + 2*(2*C_DIM*C_DIM/4))
#define PREP_BLKS ((PREP_TOTAL + 255)/256)
#define PREPALL_GRID (TRX_BLKS + TRXT_BLKS + PREP_BLKS)

__global__ void __launch_bounds__(256) prep_all(
    const float* __restrict__ x, const float* __restrict__ xt,
    const float* __restrict__ Wv, const float* __restrict__ Wk, const float* __restrict__ Wq,
    const float* __restrict__ W1, const float* __restrict__ W2)
{
    int b = blockIdx.x, tid = threadIdx.x;
    if (b < TRX_BLKS){
        transpose_body<true>(x, g_xT, g_xTr, C_DIM, S_DIM, b % (S_DIM/32),
                             (b/(S_DIM/32)) % (C_DIM/32), b/(S_DIM/32 * C_DIM/32), tid);
        return;
    }
    b -= TRX_BLKS;
    if (b < TRXT_BLKS){
        transpose_body<false>(xt, g_xtT, nullptr, T_DIM, L_DIM, b % (L_DIM/32),
                              (b/(L_DIM/32)) % (T_DIM/32), b/(L_DIM/32 * T_DIM/32), tid);
        return;
    }
    b -= TRXT_BLKS;
    int j = b*256 + tid;
    const int NVT = C_DIM*T_DIM/4, NQ = C_DIM*C_DIM/4, NF = 2*C_DIM*C_DIM/4;
    const float* src; float* dst;
    if (j < NVT){ src = Wv; dst = g_w32 + WV_OFF; }
    else if ((j -= NVT) < NVT){ src = Wk; dst = g_w32 + WK_OFF; }
    else if ((j -= NVT) < NQ ){ src = Wq; dst = g_w32 + WQ_OFF; }
    else if ((j -= NQ ) < NF ){ src = W1; dst = g_w32 + W1_OFF; }
    else if ((j -= NF ) < NF ){ src = W2; dst = g_w32 + W2_OFF; }
    else return;
    float4 v = ((const float4*)src)[j];
    v.x = to_tf32(v.x); v.y = to_tf32(v.y); v.z = to_tf32(v.z); v.w = to_tf32(v.w);
    ((float4*)dst)[j] = v;
}

// ---------------------------- generic tcgen05 GEMM (modes 0,1,2,5,6) ----------------------------
// 2 stages, distance-1 prefetch, 65KB SMEM -> 3 CTAs/SM.
#define SM_TMEM 0
#define SM_MB   16
#define SM_A(s) (1024u  + (uint32_t)(s)*16384u)
#define SM_B(s) (33792u + (uint32_t)(s)*16384u)
#define SMEM_BYTES 66560

struct GP {
    const void* A; const void* B; float* C;
    const float* tm; const float* xa; __nv_bfloat16* eb;
};

__device__ __forceinline__ void fill_async(const char* __restrict__ src, uint32_t ld_bytes,
                                           int rows, uint32_t base, int tid){
    int total = rows * 8;
    for (int idx = tid; idx < total; idx += 256){
        int row = idx >> 3, c4 = idx & 7;
        cp16(base + SWZ((uint32_t)row*128u + (uint32_t)c4*16u),
             src + (size_t)row*ld_bytes + c4*16);
    }
}

template<int MODE>
__device__ __forceinline__ void gemm_body(const GP& g, int bxx, int byy, int nb,
                                          char* smem, uint32_t sb)
{
    const int tid = threadIdx.x, wid = tid >> 5, lid = tid & 31;
    const int m0 = byy*128, n0 = bxx*128;
    constexpr int KK = (MODE==0||MODE==1) ? T_DIM : (MODE==2||MODE==5) ? C_DIM : F_DIM;
    constexpr int NT = KK / 32;
    constexpr uint32_t IDESC = (1u<<4)|(2u<<7)|(2u<<10)|(16u<<17)|(8u<<24);

    const char* Apb = nullptr; const char* Bpb = nullptr; float* Cbase = nullptr;
    uint32_t ldA = 0, ldB = 0; int ldC = 0;
    if constexpr (MODE==0){ Apb=(const char*)g.A + ((size_t)nb*L_DIM*T_DIM+(size_t)m0*T_DIM)*4; ldA=T_DIM*4;
                            Bpb=(const char*)g.B + (size_t)n0*T_DIM*4; ldB=T_DIM*4;
                            Cbase=g.C+(size_t)nb*L_DIM*C_DIM+(size_t)m0*C_DIM+n0; ldC=C_DIM; }
    if constexpr (MODE==1){ Apb=(const char*)g.A + (size_t)m0*T_DIM*4; ldA=T_DIM*4;
                            Bpb=(const char*)g.B + ((size_t)nb*L_DIM*T_DIM+(size_t)n0*T_DIM)*4; ldB=T_DIM*4;
                            ldC=L_DIM; }
    if constexpr (MODE==2){ Apb=(const char*)g.A + ((size_t)nb*S_DIM*C_DIM+(size_t)m0*C_DIM)*4; ldA=C_DIM*4;
                            Bpb=(const char*)g.B + (size_t)n0*C_DIM*4; ldB=C_DIM*4;
                            Cbase=g.C+(size_t)nb*S_DIM*C_DIM+(size_t)m0*C_DIM+n0; ldC=C_DIM; }
    if constexpr (MODE==5){ Apb=(const char*)g.A + ((size_t)nb*S_DIM*C_DIM+(size_t)m0*C_DIM)*4; ldA=C_DIM*4;
                            Bpb=(const char*)g.B + (size_t)n0*C_DIM*4; ldB=C_DIM*4;
                            Cbase=g.C+(size_t)nb*S_DIM*F_DIM+(size_t)m0*F_DIM+n0; ldC=F_DIM; }
    if constexpr (MODE==6){ Apb=(const char*)g.A + (size_t)m0*F_DIM*4; ldA=F_DIM*4;
                            Bpb=(const char*)g.B + ((size_t)nb*S_DIM*F_DIM+(size_t)n0*F_DIM)*4; ldB=F_DIM*4;
                            Cbase=g.C+(size_t)nb*C_DIM*S_DIM+(size_t)m0*S_DIM+n0; ldC=S_DIM; }

#if HAS_TC
    if (wid == 0) tc_alloc(sb + SM_TMEM, 128);
    if (tid == 0){
        mbar_init(sb + SM_MB,      1);
        mbar_init(sb + SM_MB + 16, 1);
    }
    __syncthreads();
    uint32_t tmem;
    asm volatile("ld.shared.b32 %0, [%1];" : "=r"(tmem) : "r"(sb + SM_TMEM));
    if (wid == 0) tc_relinquish();
#else
    float facc[128];
#pragma unroll
    for (int j = 0; j < 128; j++) facc[j] = 0.f;
#endif

    auto fill_tile = [&](int tt, int s){
        fill_async(Apb + (size_t)tt*128, ldA, 128, sb + SM_A(s), tid);
        fill_async(Bpb + (size_t)tt*128, ldB, 128, sb + SM_B(s), tid);
    };

    int ph[2] = {0,0};
    fill_tile(0, 0); cp_commit();

    for (int t = 0; t < NT; t++){
        const int nf = t + 1;
        if (nf < NT){
            const int s = nf & 1;
#if HAS_TC
            if (nf >= 2){ mbar_wait(sb + SM_MB + (uint32_t)s*16u, (uint32_t)ph[s]); ph[s] ^= 1; }
#endif
            fill_tile(nf, s);
        }
        cp_commit();
        cp_wait<1>();
        __syncthreads();
        const int sc = t & 1;
#if HAS_TC
        if (wid == 0 && elect_one()){
            fence_proxy();
            uint64_t ad = mk_desc(sb + SM_A(sc));
            uint64_t bd = mk_desc(sb + SM_B(sc));
#pragma unroll
            for (int c = 0; c < 4; c++)
                mma_tf32(tmem, ad + c*2, bd + c*2, IDESC, (t > 0 || c > 0) ? 1u : 0u);
            tc_commit(sb + SM_MB + (uint32_t)sc*16u);
        }
#else
        if (tid < 128){
            for (int kk = 0; kk < 32; kk++){
                float a = *(const float*)(smem + SM_A(sc) + SWZ((uint32_t)tid*128u + (uint32_t)kk*4u));
#pragma unroll
                for (int j = 0; j < 128; j++)
                    facc[j] += a * *(const float*)(smem + SM_B(sc) + SWZ((uint32_t)j*128u + (uint32_t)kk*4u));
            }
        }
        __syncthreads();
#endif
    }
#if HAS_TC
    {
        const int sl = (NT - 1) & 1;
        mbar_wait(sb + SM_MB + (uint32_t)sl*16u, (uint32_t)ph[sl]);
    }
    fence_after();
#endif

    if (wid < 4){
        const int m = wid*32 + lid;
        const float* tmb = nullptr; const float* Xrow = nullptr; __nv_bfloat16* Eb = nullptr;
        if constexpr (MODE==1){
            tmb = g.tm + (size_t)nb*L_DIM + n0;
            Eb  = g.eb + (size_t)nb*C_DIM*L_DIM + (size_t)(m0 + m)*L_DIM + n0;
        }
        if constexpr (MODE==6)
            Xrow = g.xa + (size_t)nb*C_DIM*S_DIM + (size_t)(m0 + m)*S_DIM + n0;
        float* Crow = (MODE==1) ? nullptr : Cbase + (size_t)m*ldC;

#pragma unroll
        for (int ch = 0; ch < 4; ch++){
            float v[32];
#if HAS_TC
            uint32_t r[32];
            LDTM32(r, tmem + (uint32_t)ch*32u);
            tc_wait_ld();
#pragma unroll
            for (int j = 0; j < 32; j++) v[j] = __uint_as_float(r[j]);
#else
#pragma unroll
            for (int j = 0; j < 32; j++) v[j] = facc[ch*32 + j];
#endif
            if constexpr (MODE==1){
                uint32_t pk[16];
#pragma unroll
                for (int j2 = 0; j2 < 16; j2++){
                    float t0 = tmb[ch*32 + j2*2],   a0 = v[j2*2]   * t0*t0*t0;
                    float t1 = tmb[ch*32 + j2*2+1], a1 = v[j2*2+1] * t1*t1*t1;
                    pk[j2] = pack_bf16(a0, a1);
                }
#pragma unroll
                for (int q = 0; q < 4; q++)
                    *(uint4*)(Eb + ch*32 + q*8) = make_uint4(pk[q*4],pk[q*4+1],pk[q*4+2],pk[q*4+3]);
            } else {
                if constexpr (MODE==5){
#pragma unroll
                    for (int j = 0; j < 32; j++) v[j] = to_tf32(fmaxf(v[j], 0.f));
                }
                if constexpr (MODE==0 || MODE==2){
#pragma unroll
                    for (int j = 0; j < 32; j++) v[j] = to_tf32(v[j]);
                }
                if constexpr (MODE==6){
#pragma unroll
                    for (int j4 = 0; j4 < 8; j4++){
                        float4 xv = *(const float4*)(Xrow + ch*32 + j4*4);
                        v[j4*4+0] += xv.x; v[j4*4+1] += xv.y; v[j4*4+2] += xv.z; v[j4*4+3] += xv.w;
                    }
                }
#pragma unroll
                for (int j4 = 0; j4 < 8; j4++)
                    *(float4*)(Crow + ch*32 + j4*4) =
                        make_float4(v[j4*4], v[j4*4+1], v[j4*4+2], v[j4*4+3]);
            }
        }
    }
#if HAS_TC
    __syncthreads();
    if (wid == 0) tc_dealloc(tmem, 128);
#endif
}

template<int MODE>
__global__ void __launch_bounds__(256) tc_gemm(GP g){
    extern __shared__ char smem[];
    gemm_body<MODE>(g, blockIdx.x, blockIdx.y, blockIdx.z, smem, smem_u32(smem));
}

// fused launch for the 3 independent projection GEMMs (96 + 96 + 384 CTAs)
__global__ void __launch_bounds__(256) tc_gemm012(GP g0, GP g1, GP g2){
    extern __shared__ char smem[];
    uint32_t sb = smem_u32(smem);
    int b = blockIdx.x;
    if (b < 96)       gemm_body<0>(g0, b%6, (b/6)%8, b/48, smem, sb);
    else if (b < 192){ int c = b-96;  gemm_body<1>(g1, c%8, (c/8)%6, c/48,  smem, sb); }
    else             { int c = b-192; gemm_body<2>(g2, c%6, (c/6)%32, c/192, smem, sb); }
}

// ---------------------------- fused attention kernel ----------------------------
// per CTA: one 128-row s-block of one (n,h).  q tile resident; loop 8 l-blocks:
// qk tf32 MMA -> convert (proj write, e bf16 to SMEM, denom accum) -> e@v3 bf16 MMA.
#define AT_MB    16u
#define AT_QT    1024u                         // 3 x 16384
#define AT_E     (AT_QT + 49152u)              // 32768 (2 sub-tiles of 16384)
#define AT_KT(s) (AT_E + 32768u + (uint32_t)(s)*49152u)
#define AT_V3(s) (AT_E + 32768u + 98304u + (uint32_t)(s)*24576u)
#define AT_SMEM  230400u

__global__ void __launch_bounds__(256) attn_kernel(
    const float* __restrict__ qt, const float* __restrict__ kt,
    const __nv_bfloat16* __restrict__ v3b,
    const float* __restrict__ im, const float* __restrict__ tm,
    const float* __restrict__ xTr, float* __restrict__ proj, float* __restrict__ yt)
{
    extern __shared__ char smem[];
    uint32_t sb = smem_u32(smem);
    const int tid = threadIdx.x, wid = tid >> 5, lid = tid & 31;
    const int bz = blockIdx.z, nb = bz >> 3, hh = bz & 7;
    const int m0 = blockIdx.y * 128;

    const char* Aq = (const char*)(qt  + (size_t)nb*S_DIM*C_DIM + (size_t)m0*C_DIM + hh*D_DIM);
    const char* Bk = (const char*)(kt  + (size_t)nb*L_DIM*C_DIM + hh*D_DIM);
    const char* Vb = (const char*)(v3b + (size_t)nb*C_DIM*L_DIM + (size_t)hh*D_DIM*L_DIM);
    float* Pj = proj + (size_t)bz*S_DIM*L_DIM + (size_t)m0*L_DIM;

    constexpr uint32_t ID_QK = (1u<<4)|(2u<<7)|(2u<<10)|(16u<<17)|(8u<<24);  // tf32, N=128
    constexpr uint32_t ID_PV = (1u<<4)|(1u<<7)|(1u<<10)|(12u<<17)|(8u<<24);  // bf16, N=96

#if HAS_TC
    if (wid == 0) tc_alloc(sb, 512);
    if (tid == 0){
        mbar_init(sb + AT_MB,      1);   // qk buf0
        mbar_init(sb + AT_MB + 16, 1);   // qk buf1
        mbar_init(sb + AT_MB + 32, 1);   // pv
    }
    __syncthreads();
    uint32_t tmem;
    asm volatile("ld.shared.b32 %0, [%1];" : "=r"(tmem) : "r"(sb));
    if (wid == 0) tc_relinquish();

    auto fill_kv = [&](int blk, int s){
        const char* Bkb = Bk + (size_t)blk*128*C_DIM*4;
#pragma unroll
        for (int t = 0; t < 3; t++)
            fill_async(Bkb + t*128, C_DIM*4, 128, sb + AT_KT(s) + (uint32_t)t*16384u, tid);
#pragma unroll
        for (int t2 = 0; t2 < 2; t2++)
            fill_async(Vb + (size_t)blk*256 + t2*128, L_DIM*2, 96,
                       sb + AT_V3(s) + (uint32_t)t2*12288u, tid);
    };
    auto issue_qk = [&](int blk, int buf){
        if (wid == 0 && elect_one()){
            fence_proxy();
#pragma unroll
            for (int t = 0; t < 3; t++){
                uint64_t ad = mk_desc(sb + AT_QT + (uint32_t)t*16384u);
                uint64_t bd = mk_desc(sb + AT_KT(blk&1) + (uint32_t)t*16384u);
#pragma unroll
                for (int c = 0; c < 4; c++)
                    mma_tf32(tmem + (uint32_t)buf*128u, ad + c*2, bd + c*2, ID_QK,
                             (t > 0 || c > 0) ? 1u : 0u);
            }
            tc_commit(sb + AT_MB + (uint32_t)buf*16u);
        }
    };
    auto issue_pv = [&](int blk){
        if (wid == 0 && elect_one()){
            fence_proxy();
#pragma unroll
            for (int t2 = 0; t2 < 2; t2++){
                uint64_t ad = mk_desc(sb + AT_E + (uint32_t)t2*16384u);
                uint64_t bd = mk_desc(sb + AT_V3(blk&1) + (uint32_t)t2*12288u);
#pragma unroll
                for (int c = 0; c < 4; c++)
                    mma_bf16(tmem + 256u, ad + c*2, bd + c*2, ID_PV,
                             (blk > 0 || t2 > 0 || c > 0) ? 1u : 0u);
            }
            tc_commit(sb + AT_MB + 32u);
        }
    };

    // prologue: q tile + first kv stage
#pragma unroll
    for (int t = 0; t < 3; t++)
        fill_async(Aq + t*128, C_DIM*4, 128, sb + AT_QT + (uint32_t)t*16384u, tid);
    cp_commit();
    fill_kv(0, 0);
    cp_commit();
    cp_wait<0>();
    __syncthreads();
    issue_qk(0, 0);

    // per-thread convert constants: all 8 warps convert (0-3: cols 0-63, 4-7: 64-127)
    const int mrow = (wid & 3)*32 + lid;
    const int cbase = (wid >> 2)*64;
    const float scl = im[(size_t)nb*S_DIM + m0 + mrow] * 0.1020620726159657f;
    float rsum = 0.f;

    int phq[2] = {0,0}, php = 0;
    for (int blk = 0; blk < 8; blk++){
        if (blk > 0){ mbar_wait(sb + AT_MB + 32u, (uint32_t)php); php ^= 1; }
        if (blk + 1 < 8){ fill_kv(blk + 1, (blk + 1)&1); }
        cp_commit();

        mbar_wait(sb + AT_MB + (uint32_t)(blk&1)*16u, (uint32_t)phq[blk&1]); phq[blk&1] ^= 1;
        fence_after();

        // convert coef tile D(blk&1): proj out, e bf16 to SMEM, denom accumulate
        {
            const float* tmb = tm + (size_t)nb*L_DIM + blk*128 + cbase;
            float* prow = Pj + (size_t)mrow*L_DIM + blk*128 + cbase;
#pragma unroll
            for (int ch = 0; ch < 2; ch++){
                uint32_t r[32];
                LDTM32(r, tmem + (uint32_t)(blk&1)*128u + (uint32_t)cbase + (uint32_t)ch*32u);
                tc_wait_ld();
                uint32_t pk[16]; float vv[32];
#pragma unroll
                for (int j2 = 0; j2 < 16; j2++){
                    float c0 = __uint_as_float(r[j2*2])   * scl;
                    float c1 = __uint_as_float(r[j2*2+1]) * scl;
                    float t0 = tmb[ch*32 + j2*2], t1 = tmb[ch*32 + j2*2+1];
                    float e0 = __expf(c0), e1 = __expf(c1);
                    rsum += e0*t0 + e1*t1;
                    pk[j2] = pack_bf16(e0, e1);
                    vv[j2*2]   = c0*t0;
                    vv[j2*2+1] = c1*t1;
                }
                const int col = cbase + ch*32;
                const uint32_t t2 = (uint32_t)(col >> 6);
                const uint32_t off = (uint32_t)((col & 63) * 2);
#pragma unroll
                for (int q = 0; q < 4; q++)
                    *(uint4*)(smem + AT_E + t2*16384u + SWZ((uint32_t)mrow*128u + off + (uint32_t)q*16u))
                        = make_uint4(pk[q*4],pk[q*4+1],pk[q*4+2],pk[q*4+3]);
#pragma unroll
                for (int q = 0; q < 8; q++)
                    __stcs((float4*)(prow + ch*32 + q*4),
                           make_float4(vv[q*4], vv[q*4+1], vv[q*4+2], vv[q*4+3]));
            }
        }
        __syncthreads();
        issue_pv(blk);
        if (blk + 1 < 8){
            cp_wait<0>();
            __syncthreads();
            issue_qk(blk + 1, (blk + 1)&1);
        }
    }
    mbar_wait(sb + AT_MB + 32u, (uint32_t)php);
    fence_after();

    // combine denominator halves
    float* rs = (float*)(smem + AT_E);
    rs[(wid>>2)*128 + mrow] = rsum;
    __syncthreads();

    // epilogue: xp from TMEM, scale, add x, write y_t
    if (wid < 4){
        const int m = wid*32 + lid;
        const float dv = 1.f / (rs[m] + rs[128 + m] + 1e-6f);
        const float* Xrow = xTr + (size_t)nb*S_DIM*C_DIM + (size_t)(m0 + m)*C_DIM + hh*D_DIM;
        float* Yrow = yt + (size_t)nb*S_DIM*C_DIM + (size_t)(m0 + m)*C_DIM + hh*D_DIM;
#pragma unroll
        for (int ch = 0; ch < 3; ch++){
            uint32_t r[32];
            LDTM32(r, tmem + 256u + (uint32_t)ch*32u);
            tc_wait_ld();
            float v[32];
#pragma unroll
            for (int j = 0; j < 32; j++)
                v[j] = to_tf32(__uint_as_float(r[j])*dv + Xrow[ch*32 + j]);
#pragma unroll
            for (int q = 0; q < 8; q++)
                *(float4*)(Yrow + ch*32 + q*4) = make_float4(v[q*4],v[q*4+1],v[q*4+2],v[q*4+3]);
        }
    }
    __syncthreads();
    if (wid == 0) tc_dealloc(tmem, 512);
#else
    // fallback (never executed on sm_103a hardware): naive but correct
    for (int m = tid; m < 128; m += 256){
        float scl = im[(size_t)nb*S_DIM + m0 + m] * 0.1020620726159657f;
        const float* qrow = qt + (size_t)nb*S_DIM*C_DIM + (size_t)(m0+m)*C_DIM + hh*D_DIM;
        float xp[96];
#pragma unroll
        for (int d = 0; d < 96; d++) xp[d] = 0.f;
        float rsum = 0.f;
        for (int l = 0; l < L_DIM; l++){
            const float* krow = kt + (size_t)nb*L_DIM*C_DIM + (size_t)l*C_DIM + hh*D_DIM;
            float c = 0.f;
            for (int d = 0; d < 96; d++) c += qrow[d]*krow[d];
            c *= scl;
            float t = tm[(size_t)nb*L_DIM + l];
            Pj[(size_t)m*L_DIM + l] = c*t;
            float e = expf(c);
            rsum += e*t;
            float eb = __bfloat162float(__float2bfloat16(e));
            for (int d = 0; d < 96; d++)
                xp[d] += eb * __bfloat162float(v3b[(size_t)nb*C_DIM*L_DIM + (size_t)(hh*D_DIM+d)*L_DIM + l]);
        }
        float dv = 1.f/(rsum + 1e-6f);
        for (int d = 0; d < 96; d++)
            yt[(size_t)nb*S_DIM*C_DIM + (size_t)(m0+m)*C_DIM + hh*D_DIM + d] =
                to_tf32(xp[d]*dv + xTr[(size_t)nb*S_DIM*C_DIM + (size_t)(m0+m)*C_DIM + hh*D_DIM + d]);
    }
#endif
}

// ---------------------------- host ----------------------------
extern "C" void kernel_launch(void* const* d_in, const int* in_sizes, int n_in,
                              void* d_out, int out_size)
{
    const float* x     = (const float*)d_in[0];
    const float* xt    = (const float*)d_in[1];
    const float* tmask = (const float*)d_in[2];
    const float* im    = (const float*)d_in[3];
    const float* Wv    = (const float*)d_in[4];
    const float* Wk    = (const float*)d_in[5];
    const float* Wq    = (const float*)d_in[6];
    const float* W1    = (const float*)d_in[7];
    const float* W2    = (const float*)d_in[8];
    float* outx = (float*)d_out;
    float* proj = outx + (size_t)NBATCH*C_DIM*S_DIM;

    float *pxTr, *pxT, *pxtT, *pqt, *pkt, *pyt, *pht, *pw;
    __nv_bfloat16 *pv3b;
    cudaGetSymbolAddress((void**)&pxTr, g_xTr);
    cudaGetSymbolAddress((void**)&pxT,  g_xT);
    cudaGetSymbolAddress((void**)&pxtT, g_xtT);
    cudaGetSymbolAddress((void**)&pqt,  g_qt);
    cudaGetSymbolAddress((void**)&pkt,  g_kt);
    cudaGetSymbolAddress((void**)&pyt,  g_yt);
    cudaGetSymbolAddress((void**)&pht,  g_ht);
    cudaGetSymbolAddress((void**)&pw,   g_w32);
    cudaGetSymbolAddress((void**)&pv3b, g_v3b);

    cudaFuncSetAttribute((const void*)tc_gemm012, cudaFuncAttributeMaxDynamicSharedMemorySize, SMEM_BYTES);
    cudaFuncSetAttribute((const void*)attn_kernel, cudaFuncAttributeMaxDynamicSharedMemorySize, AT_SMEM);
    cudaFuncSetAttribute((const void*)tc_gemm<5>, cudaFuncAttributeMaxDynamicSharedMemorySize, SMEM_BYTES);
    cudaFuncSetAttribute((const void*)tc_gemm<6>, cudaFuncAttributeMaxDynamicSharedMemorySize, SMEM_BYTES);

    // prep: both transposes + weight cvt, one launch
    prep_all<<<PREPALL_GRID, 256>>>(x, xt, Wv, Wk, Wq, W1, W2);

    GP g0 = {pxtT,        pw + WK_OFF, pkt,     nullptr, nullptr, nullptr};
    GP g1 = {pw + WV_OFF, pxtT,        nullptr, tmask,   nullptr, pv3b};
    GP g2 = {pxT,         pw + WQ_OFF, pqt,     nullptr, nullptr, nullptr};
    tc_gemm012<<<576, 256, SMEM_BYTES>>>(g0, g1, g2);

    // fused attention: proj (final), y_t
    attn_kernel<<<dim3(1, S_DIM/128, NHEAD), 256, AT_SMEM>>>(
        pqt, pkt, pv3b, im, tmask, pxTr, proj, pyt);

    // hmid = relu(y_t . W1^T)
    GP g5 = {pyt, pw + W1_OFF, pht, nullptr, nullptr, nullptr};
    tc_gemm<5><<<dim3(F_DIM/128, S_DIM/128, NBATCH), 256, SMEM_BYTES>>>(g5);
    // out[c][s] = x + W2 . h_t^T
    GP g6 = {pw + W2_OFF, pht, outx, nullptr, x, nullptr};
    tc_gemm<6><<<dim3(S_DIM/128, C_DIM/128, NBATCH), 256, SMEM_BYTES>>>(g6);
}